// round 3
// baseline (speedup 1.0000x reference)
#include <cuda_runtime.h>
#include <math.h>

#define NW 4           // warps (matrices) per block
#define SW32 8         // Jacobi sweeps for 32x32
#define SW16 7         // Jacobi sweeps for 16x16
#define SW4  10        // Jacobi sweeps for 4x4 (serial, cheap)

// Parallel-order (round-robin tournament) two-sided Jacobi on an n x n
// symmetric matrix held in Sw (33-stride). Accumulates eigenvectors in Vw.
// Lane l owns column l. All 32 lanes must call this (uniform n, sweeps).
__device__ __forceinline__ void jacobi_sym(float* Sw, float* Vw,
                                           float* cr, float* sr, int* pt,
                                           int l, int n, int sweeps) {
    const int m = n - 1;  // odd (31 or 15)
    for (int sw = 0; sw < sweeps; sw++) {
        for (int r = 0; r < m; r++) {
            // ---- phase 0: pairing + rotation params ----
            if (l < n) {
                int p = (l == m) ? (r % m) : ((2 * r - l + 2 * m) % m);
                if (p == l) p = m;
                pt[l] = p;
                if (l < p) {
                    float app = Sw[l * 33 + l];
                    float aqq = Sw[p * 33 + p];
                    float apq = Sw[l * 33 + p];
                    float c = 1.f, s = 0.f;
                    if (apq != 0.f) {
                        float tau = (aqq - app) / (2.f * apq);
                        float tt = 1.f / (fabsf(tau) + sqrtf(1.f + tau * tau));
                        if (tau < 0.f) tt = -tt;
                        c = 1.f / sqrtf(1.f + tt * tt);
                        s = tt * c;
                    }
                    cr[l] = c;
                    sr[l] = s;
                }
            }
            __syncwarp();
            // ---- phase 1: A <- J^T A   (lane l updates column l) ----
            if (l < n) {
                for (int i = 0; i < n; i++) {
                    int q = pt[i];
                    if (i < q) {
                        float c = cr[i], s = sr[i];
                        float a1 = Sw[i * 33 + l];
                        float a2 = Sw[q * 33 + l];
                        Sw[i * 33 + l] = c * a1 - s * a2;
                        Sw[q * 33 + l] = s * a1 + c * a2;
                    }
                }
            }
            __syncwarp();
            // ---- phase 2: A <- A J, V <- V J  (lane l updates row l) ----
            if (l < n) {
                for (int i = 0; i < n; i++) {
                    int q = pt[i];
                    if (i < q) {
                        float c = cr[i], s = sr[i];
                        float a1 = Sw[l * 33 + i];
                        float a2 = Sw[l * 33 + q];
                        Sw[l * 33 + i] = c * a1 - s * a2;
                        Sw[l * 33 + q] = s * a1 + c * a2;
                        float v1 = Vw[l * 33 + i];
                        float v2 = Vw[l * 33 + q];
                        Vw[l * 33 + i] = c * v1 - s * v2;
                        Vw[l * 33 + q] = s * v1 + c * v2;
                    }
                }
            }
            __syncwarp();
        }
    }
}

__global__ void __launch_bounds__(128)
spdnet_kernel(const float* __restrict__ x,
              const float* __restrict__ w1,
              const float* __restrict__ w2,
              const float* __restrict__ w3,
              const float* __restrict__ fc,
              float* __restrict__ out, int B) {
    // Per-warp shared tiles, 33-stride padding (odd => conflict-free rows AND cols)
    __shared__ float S_sh [NW][32 * 33];
    __shared__ float V_sh [NW][32 * 33];
    __shared__ float cr_sh[NW][32];
    __shared__ float sr_sh[NW][32];
    __shared__ int   pt_sh[NW][32];
    __shared__ float lam_sh[NW][32];
    __shared__ float w1s[32 * 32];
    __shared__ float w2s[32 * 16];
    __shared__ float w3s[16 * 4];
    __shared__ float fcs[16 * 2];

    const int tid = threadIdx.x;

    // cooperative weight load
    for (int i = tid; i < 32 * 32; i += 128) w1s[i] = w1[i];
    for (int i = tid; i < 32 * 16; i += 128) w2s[i] = w2[i];
    if (tid < 64) w3s[tid] = w3[tid];
    if (tid < 32) fcs[tid] = fc[tid];
    __syncthreads();

    const int w = tid >> 5;
    const int l = tid & 31;
    const int b = blockIdx.x * NW + w;
    if (b >= B) return;

    float* Sw = S_sh[w];
    float* Vw = V_sh[w];
    float* cr = cr_sh[w];
    float* sr = sr_sh[w];
    int*   pt = pt_sh[w];
    float* lam = lam_sh[w];

    // ---- load X (32x32 SPD) ----
    const float* xb = x + (size_t)b * 1024;
    #pragma unroll
    for (int i = 0; i < 32; i++) Sw[i * 33 + l] = xb[i * 32 + l];
    __syncwarp();

    // ---- Y1 = w1^T X w1 : lane l computes column l ----
    {
        float t[32];
        #pragma unroll
        for (int k = 0; k < 32; k++) t[k] = 0.f;
        for (int mm = 0; mm < 32; mm++) {
            float wl = w1s[mm * 32 + l];
            #pragma unroll
            for (int k = 0; k < 32; k++) t[k] += Sw[k * 33 + mm] * wl;
        }
        float y[32];
        #pragma unroll
        for (int i = 0; i < 32; i++) y[i] = 0.f;
        for (int k = 0; k < 32; k++) {
            float tk = t[k];
            #pragma unroll
            for (int i = 0; i < 32; i++) y[i] += w1s[k * 32 + i] * tk;
        }
        __syncwarp();
        #pragma unroll
        for (int i = 0; i < 32; i++) Sw[i * 33 + l] = y[i];
        #pragma unroll
        for (int i = 0; i < 32; i++) Vw[i * 33 + l] = (i == l) ? 1.f : 0.f;
        __syncwarp();
    }

    // ---- EVD #1 (32x32) ----
    jacobi_sym(Sw, Vw, cr, sr, pt, l, 32, SW32);

    // ---- rec + fold: Mh = diag(sqrt(max(lam,1e-4))) * (V^T w2)  [32x16] ----
    lam[l] = sqrtf(fmaxf(Sw[l * 33 + l], 1e-4f));
    __syncwarp();
    {
        float mrow[16];
        #pragma unroll
        for (int j = 0; j < 16; j++) mrow[j] = 0.f;
        for (int i = 0; i < 32; i++) {
            float vik = Vw[i * 33 + l];  // V[i][l]
            #pragma unroll
            for (int j = 0; j < 16; j++) mrow[j] += vik * w2s[i * 16 + j];
        }
        float sl = lam[l];
        __syncwarp();
        #pragma unroll
        for (int j = 0; j < 16; j++) Sw[l * 33 + j] = sl * mrow[j];  // Mh row l
        __syncwarp();
    }

    // ---- Y2 = Mh^T Mh  [16x16] : lane l<16 computes column l ----
    {
        float yy[16];
        if (l < 16) {
            #pragma unroll
            for (int a = 0; a < 16; a++) yy[a] = 0.f;
            for (int k = 0; k < 32; k++) {
                float skb = Sw[k * 33 + l];
                #pragma unroll
                for (int a = 0; a < 16; a++) yy[a] += Sw[k * 33 + a] * skb;
            }
        }
        __syncwarp();
        if (l < 16) {
            #pragma unroll
            for (int a = 0; a < 16; a++) Sw[a * 33 + l] = yy[a];
            #pragma unroll
            for (int i = 0; i < 16; i++) Vw[i * 33 + l] = (i == l) ? 1.f : 0.f;
        }
        __syncwarp();
    }

    // ---- EVD #2 (16x16) ----
    jacobi_sym(Sw, Vw, cr, sr, pt, l, 16, SW16);

    // ---- rec + fold: M2 = diag(sqrt(max(lam,1e-4))) * (V^T w3)  [16x4] ----
    if (l < 16) lam[l] = sqrtf(fmaxf(Sw[l * 33 + l], 1e-4f));
    __syncwarp();
    {
        float m3[4];
        if (l < 16) {
            #pragma unroll
            for (int j = 0; j < 4; j++) m3[j] = 0.f;
            for (int i = 0; i < 16; i++) {
                float vik = Vw[i * 33 + l];
                #pragma unroll
                for (int j = 0; j < 4; j++) m3[j] += vik * w3s[i * 4 + j];
            }
            float sl = lam[l];
            #pragma unroll
            for (int j = 0; j < 4; j++) m3[j] *= sl;
        }
        __syncwarp();
        if (l < 16) {
            #pragma unroll
            for (int j = 0; j < 4; j++) Sw[l * 33 + j] = m3[j];
        }
        __syncwarp();
    }

    // ---- Y3 = M2^T M2 [4x4] -> stash at cols 8..11 ----
    {
        float y3[4];
        if (l < 4) {
            #pragma unroll
            for (int a = 0; a < 4; a++) y3[a] = 0.f;
            for (int k = 0; k < 16; k++) {
                float skb = Sw[k * 33 + l];
                #pragma unroll
                for (int a = 0; a < 4; a++) y3[a] += Sw[k * 33 + a] * skb;
            }
        }
        __syncwarp();
        if (l < 4) {
            #pragma unroll
            for (int a = 0; a < 4; a++) Sw[a * 33 + 8 + l] = y3[a];
        }
        __syncwarp();
    }

    // ---- lane 0: 4x4 LogEig (serial Jacobi), feat, fc, log_softmax ----
    if (l == 0) {
        float A[4][4], Vv[4][4];
        #pragma unroll
        for (int i = 0; i < 4; i++)
            #pragma unroll
            for (int j = 0; j < 4; j++) {
                A[i][j] = Sw[i * 33 + 8 + j];
                Vv[i][j] = (i == j) ? 1.f : 0.f;
            }

#define ROT4(p, q)                                                          \
        {                                                                   \
            float apq = A[p][q];                                            \
            if (apq != 0.f) {                                               \
                float app = A[p][p], aqq = A[q][q];                         \
                float tau = (aqq - app) / (2.f * apq);                      \
                float tt = 1.f / (fabsf(tau) + sqrtf(1.f + tau * tau));     \
                if (tau < 0.f) tt = -tt;                                    \
                float c = 1.f / sqrtf(1.f + tt * tt), s = tt * c;           \
                _Pragma("unroll")                                           \
                for (int j = 0; j < 4; j++) {                               \
                    float u = A[p][j], v = A[q][j];                         \
                    A[p][j] = c * u - s * v;                                \
                    A[q][j] = s * u + c * v;                                \
                }                                                           \
                _Pragma("unroll")                                           \
                for (int j = 0; j < 4; j++) {                               \
                    float u = A[j][p], v = A[j][q];                         \
                    A[j][p] = c * u - s * v;                                \
                    A[j][q] = s * u + c * v;                                \
                }                                                           \
                _Pragma("unroll")                                           \
                for (int j = 0; j < 4; j++) {                               \
                    float u = Vv[j][p], v = Vv[j][q];                       \
                    Vv[j][p] = c * u - s * v;                               \
                    Vv[j][q] = s * u + c * v;                               \
                }                                                           \
            }                                                               \
        }

        #pragma unroll
        for (int sw = 0; sw < SW4; sw++) {
            ROT4(0, 1); ROT4(0, 2); ROT4(0, 3);
            ROT4(1, 2); ROT4(1, 3); ROT4(2, 3);
        }
#undef ROT4

        float lg[4];
        #pragma unroll
        for (int k = 0; k < 4; k++) lg[k] = logf(fmaxf(A[k][k], 1e-10f));

        float feat[16];
        #pragma unroll
        for (int i = 0; i < 4; i++)
            #pragma unroll
            for (int j = 0; j < 4; j++) {
                float acc = 0.f;
                #pragma unroll
                for (int k = 0; k < 4; k++) acc += lg[k] * Vv[i][k] * Vv[j][k];
                feat[i * 4 + j] = acc;
            }

        float l0 = 0.f, l1 = 0.f;
        #pragma unroll
        for (int i = 0; i < 16; i++) {
            l0 += feat[i] * fcs[2 * i + 0];
            l1 += feat[i] * fcs[2 * i + 1];
        }
        float mx = fmaxf(l0, l1);
        float lse = mx + logf(expf(l0 - mx) + expf(l1 - mx));

        out[2 * (size_t)b + 0] = l0 - lse;
        out[2 * (size_t)b + 1] = l1 - lse;
        float* fo = out + (size_t)2 * B + (size_t)16 * b;
        #pragma unroll
        for (int t = 0; t < 16; t++) fo[t] = feat[t];
    }
}

extern "C" void kernel_launch(void* const* d_in, const int* in_sizes, int n_in,
                              void* d_out, int out_size) {
    const float* x  = (const float*)d_in[0];
    const float* w1 = (const float*)d_in[1];
    const float* w2 = (const float*)d_in[2];
    const float* w3 = (const float*)d_in[3];
    const float* fc = (const float*)d_in[4];
    float* out = (float*)d_out;
    int B = in_sizes[0] / 1024;  // 32x32 per matrix
    dim3 grid((B + NW - 1) / NW);
    spdnet_kernel<<<grid, 128>>>(x, w1, w2, w3, fc, out, B);
}

// round 5
// speedup vs baseline: 5.4205x; 5.4205x over previous
#include <cuda_runtime.h>
#include <math.h>

#define NW 4           // warps (matrices) per block
#define SW32 8         // sweeps for 32x32 one-sided Jacobi
#define SW16 7         // sweeps for 16x16
#define SW4  10        // sweeps for 4x4 (serial, lane 0)
#define FULLMASK 0xffffffffu

// One-sided parallel Jacobi on N x N matrix, lane (idx+lanebase) holds column
// idx in g[N]. Tournament pairing, all 32 lanes participate (for N=16 the two
// half-warps hold mirrored copies). Returns the exact final squared column
// norm (= lambda^2). After return: lambda = sqrt(ret), eigvec = g / lambda.
template<int N>
__device__ __forceinline__ float jacobi1s(float (&g)[N], int idx, int lanebase,
                                          int sweeps) {
    const int m = N - 1;  // odd
    for (int sw = 0; sw < sweeps; sw++) {
        // recompute own squared norm at sweep start (kills drift)
        float n_own;
        {
            float d0 = 0.f, d1 = 0.f, d2 = 0.f, d3 = 0.f;
            #pragma unroll
            for (int i = 0; i < N; i += 4) {
                d0 = fmaf(g[i + 0], g[i + 0], d0);
                d1 = fmaf(g[i + 1], g[i + 1], d1);
                d2 = fmaf(g[i + 2], g[i + 2], d2);
                d3 = fmaf(g[i + 3], g[i + 3], d3);
            }
            n_own = (d0 + d1) + (d2 + d3);
        }
        for (int r = 0; r < m; r++) {
            int p = (idx == m) ? (r % m) : ((2 * r - idx + 2 * m) % m);
            if (p == idx) p = m;
            int src = p + lanebase;
            float t[N];
            #pragma unroll
            for (int i = 0; i < N; i++) t[i] = __shfl_sync(FULLMASK, g[i], src);
            float np = __shfl_sync(FULLMASK, n_own, src);
            // d = g . t  (bit-identical on both lanes of the pair)
            float d0 = 0.f, d1 = 0.f, d2 = 0.f, d3 = 0.f;
            #pragma unroll
            for (int i = 0; i < N; i += 4) {
                d0 = fmaf(g[i + 0], t[i + 0], d0);
                d1 = fmaf(g[i + 1], t[i + 1], d1);
                d2 = fmaf(g[i + 2], t[i + 2], d2);
                d3 = fmaf(g[i + 3], t[i + 3], d3);
            }
            float d = (d0 + d1) + (d2 + d3);
            if (fabsf(d) > 1e-30f) {
                float tt;
                if (np == n_own) {
                    // exact tie: explicit antisymmetric 45-degree rotation
                    tt = (idx < p) ? 1.f : -1.f;
                } else {
                    float tau = (np - n_own) * 0.5f / d;  // exact-negated on partner
                    tt = 1.f / (fabsf(tau) + sqrtf(fmaf(tau, tau, 1.f)));
                    if (tau < 0.f) tt = -tt;
                }
                float c = rsqrtf(fmaf(tt, tt, 1.f));  // identical on both lanes
                float s = tt * c;                     // sign-mirrored
                #pragma unroll
                for (int i = 0; i < N; i++) g[i] = fmaf(c, g[i], -s * t[i]);
                n_own = fmaf(c * c, n_own, fmaf(s * s, np, -2.f * c * s * d));
            }
        }
    }
    // exact final squared norm
    float d0 = 0.f, d1 = 0.f, d2 = 0.f, d3 = 0.f;
    #pragma unroll
    for (int i = 0; i < N; i += 4) {
        d0 = fmaf(g[i + 0], g[i + 0], d0);
        d1 = fmaf(g[i + 1], g[i + 1], d1);
        d2 = fmaf(g[i + 2], g[i + 2], d2);
        d3 = fmaf(g[i + 3], g[i + 3], d3);
    }
    return (d0 + d1) + (d2 + d3);
}

__global__ void __launch_bounds__(128)
spdnet_kernel(const float* __restrict__ x,
              const float* __restrict__ w1,
              const float* __restrict__ w2,
              const float* __restrict__ w3,
              const float* __restrict__ fc,
              float* __restrict__ out, int B) {
    __shared__ float S_sh[NW][32 * 33];  // per-warp staging tile
    __shared__ float w1s[32 * 32];
    __shared__ float w2s[32 * 16];
    __shared__ float w3s[16 * 4];
    __shared__ float fcs[16 * 2];

    const int tid = threadIdx.x;
    for (int i = tid; i < 32 * 32; i += 128) w1s[i] = w1[i];
    for (int i = tid; i < 32 * 16; i += 128) w2s[i] = w2[i];
    if (tid < 64) w3s[tid] = w3[tid];
    if (tid < 32) fcs[tid] = fc[tid];
    __syncthreads();

    const int w = tid >> 5;
    const int l = tid & 31;
    const int b = blockIdx.x * NW + w;
    if (b >= B) return;  // warp-uniform

    float* Sw = S_sh[w];

    // ---- stage X (32x32) into smem ----
    const float* xb = x + (size_t)b * 1024;
    #pragma unroll
    for (int i = 0; i < 32; i++) Sw[i * 33 + l] = xb[i * 32 + l];
    __syncwarp();

    // ---- g = column l of Y1 = w1^T X w1 ----
    float g[32];
    {
        float t[32];
        #pragma unroll
        for (int k = 0; k < 32; k++) t[k] = 0.f;
        for (int mm = 0; mm < 32; mm++) {
            float wl = w1s[mm * 32 + l];
            #pragma unroll
            for (int k = 0; k < 32; k++) t[k] = fmaf(Sw[k * 33 + mm], wl, t[k]);
        }
        #pragma unroll
        for (int i = 0; i < 32; i++) g[i] = 0.f;
        for (int k = 0; k < 32; k++) {
            float tk = t[k];
            #pragma unroll
            for (int i = 0; i < 32; i++) g[i] = fmaf(w1s[k * 32 + i], tk, g[i]);
        }
    }
    __syncwarp();

    // ---- EVD #1 (one-sided Jacobi, registers) ----
    float n1 = jacobi1s<32>(g, l, 0, SW32);
    float lam1 = sqrtf(fmaxf(n1, 1e-20f));
    float coef1 = sqrtf(fmaxf(lam1, 1e-4f)) / lam1;  // sqrt(clamped)/lam

    // ---- Mh[l][j] = coef1 * sum_i g[i] * w2[i][j]   (row l of 32x16 Mh) ----
    {
        float mh[16];
        #pragma unroll
        for (int j = 0; j < 16; j++) mh[j] = 0.f;
        #pragma unroll
        for (int i = 0; i < 32; i++) {
            float gi = g[i];
            #pragma unroll
            for (int j = 0; j < 16; j++) mh[j] = fmaf(gi, w2s[i * 16 + j], mh[j]);
        }
        __syncwarp();
        #pragma unroll
        for (int j = 0; j < 16; j++) Sw[l * 17 + j] = coef1 * mh[j];
        __syncwarp();
    }

    // ---- Y2 = Mh^T Mh (16x16); lane's column (mirrored across half-warps) ----
    const int l16 = l & 15;
    float g2[16];
    {
        #pragma unroll
        for (int a = 0; a < 16; a++) g2[a] = 0.f;
        for (int k = 0; k < 32; k++) {
            float mkl = Sw[k * 17 + l16];
            #pragma unroll
            for (int a = 0; a < 16; a++) g2[a] = fmaf(Sw[k * 17 + a], mkl, g2[a]);
        }
    }

    // ---- EVD #2 (16x16) ----
    float n2 = jacobi1s<16>(g2, l16, l & 16, SW16);
    float lam2 = sqrtf(fmaxf(n2, 1e-20f));
    float coef2 = sqrtf(fmaxf(lam2, 1e-4f)) / lam2;

    // ---- M2[l16][j] = coef2 * sum_i g2[i] * w3[i][j]  (16x4) ----
    {
        float m2[4];
        #pragma unroll
        for (int j = 0; j < 4; j++) m2[j] = 0.f;
        #pragma unroll
        for (int i = 0; i < 16; i++) {
            float gi = g2[i];
            #pragma unroll
            for (int j = 0; j < 4; j++) m2[j] = fmaf(gi, w3s[i * 4 + j], m2[j]);
        }
        __syncwarp();
        if (l < 16) {
            #pragma unroll
            for (int j = 0; j < 4; j++) Sw[l * 5 + j] = coef2 * m2[j];
        }
        __syncwarp();
    }

    // ---- Y3 = M2^T M2 (4x4): lane l<16 computes entry (l>>2, l&3) ----
    if (l < 16) {
        int a = l >> 2, c = l & 3;
        float acc = 0.f;
        #pragma unroll
        for (int k = 0; k < 16; k++) acc = fmaf(Sw[k * 5 + a], Sw[k * 5 + c], acc);
        Sw[96 + l] = acc;
    }
    __syncwarp();

    // ---- lane 0: 4x4 LogEig (serial Jacobi), feat, fc, log_softmax ----
    if (l == 0) {
        float A[4][4], Vv[4][4];
        #pragma unroll
        for (int i = 0; i < 4; i++)
            #pragma unroll
            for (int j = 0; j < 4; j++) {
                A[i][j] = Sw[96 + i * 4 + j];
                Vv[i][j] = (i == j) ? 1.f : 0.f;
            }

#define ROT4(p, q)                                                          \
        {                                                                   \
            float apq = A[p][q];                                            \
            if (apq != 0.f) {                                               \
                float app = A[p][p], aqq = A[q][q];                         \
                float tau = (aqq - app) / (2.f * apq);                      \
                float tt = 1.f / (fabsf(tau) + sqrtf(1.f + tau * tau));     \
                if (tau < 0.f) tt = -tt;                                    \
                float c = 1.f / sqrtf(1.f + tt * tt), s = tt * c;           \
                _Pragma("unroll")                                           \
                for (int j = 0; j < 4; j++) {                               \
                    float u = A[p][j], v = A[q][j];                         \
                    A[p][j] = c * u - s * v;                                \
                    A[q][j] = s * u + c * v;                                \
                }                                                           \
                _Pragma("unroll")                                           \
                for (int j = 0; j < 4; j++) {                               \
                    float u = A[j][p], v = A[j][q];                         \
                    A[j][p] = c * u - s * v;                                \
                    A[j][q] = s * u + c * v;                                \
                }                                                           \
                _Pragma("unroll")                                           \
                for (int j = 0; j < 4; j++) {                               \
                    float u = Vv[j][p], v = Vv[j][q];                       \
                    Vv[j][p] = c * u - s * v;                               \
                    Vv[j][q] = s * u + c * v;                               \
                }                                                           \
            }                                                               \
        }

        #pragma unroll
        for (int sw = 0; sw < SW4; sw++) {
            ROT4(0, 1); ROT4(0, 2); ROT4(0, 3);
            ROT4(1, 2); ROT4(1, 3); ROT4(2, 3);
        }
#undef ROT4

        float lg[4];
        #pragma unroll
        for (int k = 0; k < 4; k++) lg[k] = logf(fmaxf(A[k][k], 1e-10f));

        float feat[16];
        #pragma unroll
        for (int i = 0; i < 4; i++)
            #pragma unroll
            for (int j = 0; j < 4; j++) {
                float acc = 0.f;
                #pragma unroll
                for (int k = 0; k < 4; k++) acc += lg[k] * Vv[i][k] * Vv[j][k];
                feat[i * 4 + j] = acc;
            }

        float l0 = 0.f, l1 = 0.f;
        #pragma unroll
        for (int i = 0; i < 16; i++) {
            l0 += feat[i] * fcs[2 * i + 0];
            l1 += feat[i] * fcs[2 * i + 1];
        }
        float mx = fmaxf(l0, l1);
        float lse = mx + logf(expf(l0 - mx) + expf(l1 - mx));

        out[2 * (size_t)b + 0] = l0 - lse;
        out[2 * (size_t)b + 1] = l1 - lse;
        float* fo = out + (size_t)2 * B + (size_t)16 * b;
        #pragma unroll
        for (int t2 = 0; t2 < 16; t2++) fo[t2] = feat[t2];
    }
}

extern "C" void kernel_launch(void* const* d_in, const int* in_sizes, int n_in,
                              void* d_out, int out_size) {
    const float* x  = (const float*)d_in[0];
    const float* w1 = (const float*)d_in[1];
    const float* w2 = (const float*)d_in[2];
    const float* w3 = (const float*)d_in[3];
    const float* fc = (const float*)d_in[4];
    float* out = (float*)d_out;
    int B = in_sizes[0] / 1024;
    dim3 grid((B + NW - 1) / NW);
    spdnet_kernel<<<grid, 128>>>(x, w1, w2, w3, fc, out, B);
}

// round 6
// speedup vs baseline: 6.5327x; 1.2052x over previous
#include <cuda_runtime.h>
#include <math.h>

#define NW 4           // warps (matrices) per block
#define SW32 6         // sweeps for 32x32 one-sided Jacobi
#define SW16 6         // sweeps for 16x16
#define SW4  10        // sweeps for 4x4 (serial, lane 0)
#define FULLMASK 0xffffffffu

typedef unsigned long long u64;

// ---- packed f32x2 helpers (sm_103a FFMA2 path) ----
__device__ __forceinline__ u64 pk2(float lo, float hi) {
    u64 r; asm("mov.b64 %0,{%1,%2};" : "=l"(r) : "f"(lo), "f"(hi)); return r;
}
__device__ __forceinline__ void up2(u64 v, float& lo, float& hi) {
    asm("mov.b64 {%0,%1},%2;" : "=f"(lo), "=f"(hi) : "l"(v));
}
__device__ __forceinline__ u64 f2fma(u64 a, u64 b, u64 c) {
    u64 d; asm("fma.rn.f32x2 %0,%1,%2,%3;" : "=l"(d) : "l"(a), "l"(b), "l"(c)); return d;
}
__device__ __forceinline__ u64 f2mul(u64 a, u64 b) {
    u64 d; asm("mul.rn.f32x2 %0,%1,%2;" : "=l"(d) : "l"(a), "l"(b)); return d;
}

// One-sided parallel Jacobi, packed columns. Lane (idx+lanebase) holds column
// idx as N2 f32x2 registers. Tournament pairing (incremental, no modulo).
// Returns final squared column norm (= lambda^2); eigvec = g / lambda.
template<int N2>
__device__ __forceinline__ float jacobi1s_pk(u64 (&g)[N2], int idx, int lanebase,
                                             int sweeps) {
    const int m = 2 * N2 - 1;  // odd
    float n_own = 0.f;
    for (int sw = 0; sw < sweeps; sw++) {
        // recompute own squared norm at sweep start (kills drift)
        {
            u64 a0 = 0ull, a1 = 0ull;
            #pragma unroll
            for (int i = 0; i < N2; i += 2) {
                a0 = f2fma(g[i], g[i], a0);
                a1 = f2fma(g[i + 1], g[i + 1], a1);
            }
            float x0, y0, x1, y1; up2(a0, x0, y0); up2(a1, x1, y1);
            n_own = (x0 + y0) + (x1 + y1);
        }
        int pb = (idx == 0) ? 0 : (m - idx);  // (2r - idx) mod m, incremental
        for (int r = 0; r < m; r++) {
            int p = (idx == m) ? r : ((pb == idx) ? m : pb);
            pb += 2; if (pb >= m) pb -= m;
            int src = p + lanebase;
            u64 t[N2];
            #pragma unroll
            for (int i = 0; i < N2; i++) t[i] = __shfl_sync(FULLMASK, g[i], src);
            float np = __shfl_sync(FULLMASK, n_own, src);
            // d = g . t  (bit-identical on both lanes of the pair)
            u64 b0 = 0ull, b1 = 0ull;
            #pragma unroll
            for (int i = 0; i < N2; i += 2) {
                b0 = f2fma(g[i], t[i], b0);
                b1 = f2fma(g[i + 1], t[i + 1], b1);
            }
            float x0, y0, x1, y1; up2(b0, x0, y0); up2(b1, x1, y1);
            float d = (x0 + y0) + (x1 + y1);
            if (fabsf(d) > 1e-30f) {
                float tt;
                if (np == n_own) {
                    tt = (idx < p) ? 1.f : -1.f;  // exact tie: 45-deg antisym
                } else {
                    float tau = (np - n_own) * 0.5f / d;  // exact-negated on partner
                    tt = 1.f / (fabsf(tau) + sqrtf(fmaf(tau, tau, 1.f)));
                    if (tau < 0.f) tt = -tt;
                }
                float c = rsqrtf(fmaf(tt, tt, 1.f));  // identical on both lanes
                float s = tt * c;                     // sign-mirrored
                u64 cp = pk2(c, c), ns = pk2(-s, -s);
                #pragma unroll
                for (int i = 0; i < N2; i++) g[i] = f2fma(cp, g[i], f2mul(ns, t[i]));
                n_own = fmaf(c * c, n_own, fmaf(s * s, np, -2.f * c * s * d));
            }
        }
    }
    u64 a0 = 0ull, a1 = 0ull;
    #pragma unroll
    for (int i = 0; i < N2; i += 2) {
        a0 = f2fma(g[i], g[i], a0);
        a1 = f2fma(g[i + 1], g[i + 1], a1);
    }
    float x0, y0, x1, y1; up2(a0, x0, y0); up2(a1, x1, y1);
    return (x0 + y0) + (x1 + y1);
}

__global__ void __launch_bounds__(128)
spdnet_kernel(const float* __restrict__ x,
              const float* __restrict__ w1,
              const float* __restrict__ w2,
              const float* __restrict__ w3,
              const float* __restrict__ fc,
              float* __restrict__ out, int B) {
    __shared__ float S_sh[NW][32 * 32];   // per-warp staging (stride 32, u64-aligned rows)
    __shared__ float w1s [32 * 32];       // w1 row-major
    __shared__ float w1Ts[32 * 32];       // w1 transposed (col l contiguous)
    __shared__ float w2s [32 * 16];
    __shared__ float w3s [16 * 4];
    __shared__ float fcs [16 * 2];

    const int tid = threadIdx.x;
    for (int i = tid; i < 32 * 32; i += 128) w1s[i] = w1[i];
    for (int i = tid; i < 32 * 32; i += 128)
        w1Ts[i] = w1[(i & 31) * 32 + (i >> 5)];  // conflict-free stores
    for (int i = tid; i < 32 * 16; i += 128) w2s[i] = w2[i];
    if (tid < 64) w3s[tid] = w3[tid];
    if (tid < 32) fcs[tid] = fc[tid];
    __syncthreads();

    const int w = tid >> 5;
    const int l = tid & 31;
    const int b = blockIdx.x * NW + w;
    if (b >= B) return;  // warp-uniform

    float* Sw = S_sh[w];

    // ---- stage X (32x32), stride 32 (lane-stride-1 writes: conflict-free) ----
    const float* xb = x + (size_t)b * 1024;
    #pragma unroll
    for (int i = 0; i < 32; i++) Sw[i * 32 + l] = xb[i * 32 + l];
    __syncwarp();

    // ---- g = column l of Y1 = w1^T X w1, fused + packed ----
    u64 g[16];
    {
        u64 wr[16];  // w1 column l, packed (hoisted for all k)
        const u64* w1Trow = (const u64*)(w1Ts + l * 32);
        #pragma unroll
        for (int i = 0; i < 16; i++) wr[i] = w1Trow[i];
        #pragma unroll
        for (int i = 0; i < 16; i++) g[i] = 0ull;
        for (int k = 0; k < 32; k++) {
            const u64* xrow = (const u64*)(Sw + k * 32);    // broadcast reads
            u64 a0 = 0ull, a1 = 0ull;
            #pragma unroll
            for (int i = 0; i < 16; i += 2) {
                a0 = f2fma(xrow[i], wr[i], a0);
                a1 = f2fma(xrow[i + 1], wr[i + 1], a1);
            }
            float x0, y0, x1, y1; up2(a0, x0, y0); up2(a1, x1, y1);
            float tk = (x0 + y0) + (x1 + y1);                // T[k][l]
            u64 tk2 = pk2(tk, tk);
            const u64* w1row = (const u64*)(w1s + k * 32);   // broadcast reads
            #pragma unroll
            for (int i = 0; i < 16; i++) g[i] = f2fma(w1row[i], tk2, g[i]);
        }
    }
    __syncwarp();

    // ---- EVD #1 (one-sided Jacobi, packed registers) ----
    float n1 = jacobi1s_pk<16>(g, l, 0, SW32);
    float lam1 = sqrtf(fmaxf(n1, 1e-20f));
    float coef1 = sqrtf(fmaxf(lam1, 1e-4f)) / lam1;  // sqrt(clamped)/lam

    // ---- Mh[l][j] = coef1 * sum_i g[i] * w2[i][j]  (row l of 32x16), packed ----
    {
        u64 mh[8];
        #pragma unroll
        for (int j = 0; j < 8; j++) mh[j] = 0ull;
        #pragma unroll
        for (int i2 = 0; i2 < 16; i2++) {
            float glo, ghi; up2(g[i2], glo, ghi);
            u64 ga = pk2(glo, glo), gb = pk2(ghi, ghi);
            const u64* r0 = (const u64*)(w2s + (2 * i2) * 16);
            const u64* r1 = (const u64*)(w2s + (2 * i2 + 1) * 16);
            #pragma unroll
            for (int j = 0; j < 8; j++) {
                mh[j] = f2fma(ga, r0[j], mh[j]);
                mh[j] = f2fma(gb, r1[j], mh[j]);
            }
        }
        __syncwarp();
        #pragma unroll
        for (int j = 0; j < 8; j++) {
            float a, c2; up2(mh[j], a, c2);
            Sw[l * 17 + 2 * j]     = coef1 * a;   // stride 17: conflict-free
            Sw[l * 17 + 2 * j + 1] = coef1 * c2;
        }
        __syncwarp();
    }

    // ---- Y2 = Mh^T Mh (16x16); lane's column (mirrored across half-warps) ----
    const int l16 = l & 15;
    float g2s[16];
    {
        #pragma unroll
        for (int a = 0; a < 16; a++) g2s[a] = 0.f;
        for (int k = 0; k < 32; k++) {
            float mkl = Sw[k * 17 + l16];
            #pragma unroll
            for (int a = 0; a < 16; a++) g2s[a] = fmaf(Sw[k * 17 + a], mkl, g2s[a]);
        }
    }
    u64 g2[8];
    #pragma unroll
    for (int i = 0; i < 8; i++) g2[i] = pk2(g2s[2 * i], g2s[2 * i + 1]);

    // ---- EVD #2 (16x16, packed) ----
    float n2 = jacobi1s_pk<8>(g2, l16, l & 16, SW16);
    float lam2 = sqrtf(fmaxf(n2, 1e-20f));
    float coef2 = sqrtf(fmaxf(lam2, 1e-4f)) / lam2;

    // ---- M2[l16][j] = coef2 * sum_i g2[i] * w3[i][j]  (16x4) ----
    {
        float m2[4] = {0.f, 0.f, 0.f, 0.f};
        #pragma unroll
        for (int i2 = 0; i2 < 8; i2++) {
            float glo, ghi; up2(g2[i2], glo, ghi);
            #pragma unroll
            for (int j = 0; j < 4; j++) {
                m2[j] = fmaf(glo, w3s[(2 * i2) * 4 + j], m2[j]);
                m2[j] = fmaf(ghi, w3s[(2 * i2 + 1) * 4 + j], m2[j]);
            }
        }
        __syncwarp();
        if (l < 16) {
            #pragma unroll
            for (int j = 0; j < 4; j++) Sw[l * 5 + j] = coef2 * m2[j];
        }
        __syncwarp();
    }

    // ---- Y3 = M2^T M2 (4x4): lane l<16 computes entry (l>>2, l&3) ----
    if (l < 16) {
        int a = l >> 2, c = l & 3;
        float acc = 0.f;
        #pragma unroll
        for (int k = 0; k < 16; k++) acc = fmaf(Sw[k * 5 + a], Sw[k * 5 + c], acc);
        Sw[96 + l] = acc;
    }
    __syncwarp();

    // ---- lane 0: 4x4 LogEig (serial Jacobi), feat, fc, log_softmax ----
    if (l == 0) {
        float A[4][4], Vv[4][4];
        #pragma unroll
        for (int i = 0; i < 4; i++)
            #pragma unroll
            for (int j = 0; j < 4; j++) {
                A[i][j] = Sw[96 + i * 4 + j];
                Vv[i][j] = (i == j) ? 1.f : 0.f;
            }

#define ROT4(p, q)                                                          \
        {                                                                   \
            float apq = A[p][q];                                            \
            if (apq != 0.f) {                                               \
                float app = A[p][p], aqq = A[q][q];                         \
                float tau = (aqq - app) / (2.f * apq);                      \
                float tt = 1.f / (fabsf(tau) + sqrtf(1.f + tau * tau));     \
                if (tau < 0.f) tt = -tt;                                    \
                float c = 1.f / sqrtf(1.f + tt * tt), s = tt * c;           \
                _Pragma("unroll")                                           \
                for (int j = 0; j < 4; j++) {                               \
                    float u = A[p][j], v = A[q][j];                         \
                    A[p][j] = c * u - s * v;                                \
                    A[q][j] = s * u + c * v;                                \
                }                                                           \
                _Pragma("unroll")                                           \
                for (int j = 0; j < 4; j++) {                               \
                    float u = A[j][p], v = A[j][q];                         \
                    A[j][p] = c * u - s * v;                                \
                    A[j][q] = s * u + c * v;                                \
                }                                                           \
                _Pragma("unroll")                                           \
                for (int j = 0; j < 4; j++) {                               \
                    float u = Vv[j][p], v = Vv[j][q];                       \
                    Vv[j][p] = c * u - s * v;                               \
                    Vv[j][q] = s * u + c * v;                               \
                }                                                           \
            }                                                               \
        }

        #pragma unroll
        for (int sw = 0; sw < SW4; sw++) {
            ROT4(0, 1); ROT4(0, 2); ROT4(0, 3);
            ROT4(1, 2); ROT4(1, 3); ROT4(2, 3);
        }
#undef ROT4

        float lg[4];
        #pragma unroll
        for (int k = 0; k < 4; k++) lg[k] = logf(fmaxf(A[k][k], 1e-10f));

        float feat[16];
        #pragma unroll
        for (int i = 0; i < 4; i++)
            #pragma unroll
            for (int j = 0; j < 4; j++) {
                float acc = 0.f;
                #pragma unroll
                for (int k = 0; k < 4; k++) acc += lg[k] * Vv[i][k] * Vv[j][k];
                feat[i * 4 + j] = acc;
            }

        float l0 = 0.f, l1 = 0.f;
        #pragma unroll
        for (int i = 0; i < 16; i++) {
            l0 += feat[i] * fcs[2 * i + 0];
            l1 += feat[i] * fcs[2 * i + 1];
        }
        float mx = fmaxf(l0, l1);
        float lse = mx + logf(expf(l0 - mx) + expf(l1 - mx));

        out[2 * (size_t)b + 0] = l0 - lse;
        out[2 * (size_t)b + 1] = l1 - lse;
        float* fo = out + (size_t)2 * B + (size_t)16 * b;
        #pragma unroll
        for (int t2 = 0; t2 < 16; t2++) fo[t2] = feat[t2];
    }
}

extern "C" void kernel_launch(void* const* d_in, const int* in_sizes, int n_in,
                              void* d_out, int out_size) {
    const float* x  = (const float*)d_in[0];
    const float* w1 = (const float*)d_in[1];
    const float* w2 = (const float*)d_in[2];
    const float* w3 = (const float*)d_in[3];
    const float* fc = (const float*)d_in[4];
    float* out = (float*)d_out;
    int B = in_sizes[0] / 1024;
    dim3 grid((B + NW - 1) / NW);
    spdnet_kernel<<<grid, 128>>>(x, w1, w2, w3, fc, out, B);
}

// round 9
// speedup vs baseline: 8.2963x; 1.2700x over previous
#include <cuda_runtime.h>
#include <math.h>

#define NW 4           // warps (matrices) per block
#define SW32 6         // sweeps for 32x32 one-sided Jacobi
#define SW16 6         // sweeps for 16x16
#define SW4  7         // sweeps for 4x4 (serial, lane 0)
#define FULLMASK 0xffffffffu

typedef unsigned long long u64;

// ---- packed f32x2 helpers (sm_103a FFMA2 path) ----
__device__ __forceinline__ u64 pk2(float lo, float hi) {
    u64 r; asm("mov.b64 %0,{%1,%2};" : "=l"(r) : "f"(lo), "f"(hi)); return r;
}
__device__ __forceinline__ void up2(u64 v, float& lo, float& hi) {
    asm("mov.b64 {%0,%1},%2;" : "=f"(lo), "=f"(hi) : "l"(v));
}
__device__ __forceinline__ u64 f2fma(u64 a, u64 b, u64 c) {
    u64 d; asm("fma.rn.f32x2 %0,%1,%2,%3;" : "=l"(d) : "l"(a), "l"(b), "l"(c)); return d;
}
__device__ __forceinline__ u64 f2mul(u64 a, u64 b) {
    u64 d; asm("mul.rn.f32x2 %0,%1,%2;" : "=l"(d) : "l"(a), "l"(b)); return d;
}
// ---- approx MUFU (single-instruction) ----
__device__ __forceinline__ float frcp(float x) {
    float r; asm("rcp.approx.f32 %0,%1;" : "=f"(r) : "f"(x)); return r;
}
__device__ __forceinline__ float fsqrt_ap(float x) {
    float r; asm("sqrt.approx.f32 %0,%1;" : "=f"(r) : "f"(x)); return r;
}
__device__ __forceinline__ float frsqrt_ap(float x) {
    float r; asm("rsqrt.approx.f32 %0,%1;" : "=f"(r) : "f"(x)); return r;
}

// One-sided parallel Jacobi, packed columns. Lane (idx+lanebase) holds column
// idx as N2 f32x2 registers. Tournament pairing (incremental, no modulo).
// Branchless rotation: approx-MUFU params; degenerate cases resolve to
// identity (d->0 => tau->inf => tt->0) except the exact-tie select.
// Returns final squared column norm (= lambda^2); eigvec = g / lambda.
template<int N2>
__device__ __forceinline__ float jacobi1s_pk(u64 (&g)[N2], int idx, int lanebase,
                                             int sweeps) {
    const int m = 2 * N2 - 1;  // odd
    float n_own = 0.f;
    for (int sw = 0; sw < sweeps; sw++) {
        // recompute own squared norm at sweep start (kills drift)
        {
            u64 a0 = 0ull, a1 = 0ull;
            #pragma unroll
            for (int i = 0; i < N2; i += 2) {
                a0 = f2fma(g[i], g[i], a0);
                a1 = f2fma(g[i + 1], g[i + 1], a1);
            }
            float x0, y0, x1, y1; up2(a0, x0, y0); up2(a1, x1, y1);
            n_own = (x0 + y0) + (x1 + y1);
        }
        int pb = (idx == 0) ? 0 : (m - idx);  // (2r - idx) mod m, incremental
        for (int r = 0; r < m; r++) {
            int p = (idx == m) ? r : ((pb == idx) ? m : pb);
            pb += 2; if (pb >= m) pb -= m;
            int src = p + lanebase;
            u64 t[N2];
            #pragma unroll
            for (int i = 0; i < N2; i++) t[i] = __shfl_sync(FULLMASK, g[i], src);
            float np = __shfl_sync(FULLMASK, n_own, src);
            // d = g . t  (bit-identical on both lanes of the pair)
            u64 b0 = 0ull, b1 = 0ull;
            #pragma unroll
            for (int i = 0; i < N2; i += 2) {
                b0 = f2fma(g[i], t[i], b0);
                b1 = f2fma(g[i + 1], t[i + 1], b1);
            }
            float x0, y0, x1, y1; up2(b0, x0, y0); up2(b1, x1, y1);
            float d = (x0 + y0) + (x1 + y1);
            // rotation params (exactly sign-mirrored on partner lane)
            float dn = (np - n_own) * 0.5f;          // exactly negated on partner
            float tau = dn * frcp(d);                // d==0 => +-inf (or NaN if tie)
            float st = fsqrt_ap(fmaf(tau, tau, 1.f));
            float tt = frcp(fabsf(tau) + st);        // tau inf => tt 0 => identity
            tt = (tau < 0.f) ? -tt : tt;
            if (np == n_own) tt = (idx < p) ? 1.f : -1.f;  // tie: 45-deg antisym
            float c = frsqrt_ap(fmaf(tt, tt, 1.f));  // identical on both lanes
            float s = tt * c;                        // sign-mirrored
            u64 cp = pk2(c, c), ns = pk2(-s, -s);
            #pragma unroll
            for (int i = 0; i < N2; i++) g[i] = f2fma(cp, g[i], f2mul(ns, t[i]));
            n_own = fmaf(c * c, n_own, fmaf(s * s, np, -2.f * c * s * d));
        }
    }
    u64 a0 = 0ull, a1 = 0ull;
    #pragma unroll
    for (int i = 0; i < N2; i += 2) {
        a0 = f2fma(g[i], g[i], a0);
        a1 = f2fma(g[i + 1], g[i + 1], a1);
    }
    float x0, y0, x1, y1; up2(a0, x0, y0); up2(a1, x1, y1);
    return (x0 + y0) + (x1 + y1);
}

__global__ void __launch_bounds__(128)
spdnet_kernel(const float* __restrict__ x,
              const float* __restrict__ w1,
              const float* __restrict__ w2,
              const float* __restrict__ w3,
              const float* __restrict__ fc,
              float* __restrict__ out, int B) {
    __shared__ float S_sh[NW][32 * 32];   // per-warp staging (stride 32, u64-aligned rows)
    __shared__ float w1s [32 * 32];       // w1 row-major
    __shared__ float w1Ts[32 * 32];       // w1 transposed (col l contiguous)
    __shared__ float w2s [32 * 16];
    __shared__ float w3s [16 * 4];
    __shared__ float fcs [16 * 2];

    const int tid = threadIdx.x;
    for (int i = tid; i < 32 * 32; i += 128) w1s[i] = w1[i];
    for (int i = tid; i < 32 * 32; i += 128)
        w1Ts[i] = w1[(i & 31) * 32 + (i >> 5)];  // conflict-free stores
    for (int i = tid; i < 32 * 16; i += 128) w2s[i] = w2[i];
    if (tid < 64) w3s[tid] = w3[tid];
    if (tid < 32) fcs[tid] = fc[tid];
    __syncthreads();

    const int w = tid >> 5;
    const int l = tid & 31;
    const int b = blockIdx.x * NW + w;
    if (b >= B) return;  // warp-uniform

    float* Sw = S_sh[w];

    // ---- stage X (32x32), stride 32 (lane-stride-1 writes: conflict-free) ----
    const float* xb = x + (size_t)b * 1024;
    #pragma unroll
    for (int i = 0; i < 32; i++) Sw[i * 32 + l] = xb[i * 32 + l];
    __syncwarp();

    // ---- g = column l of Y1 = w1^T X w1, fused + packed ----
    u64 g[16];
    {
        u64 wr[16];  // w1 column l, packed (hoisted for all k)
        const u64* w1Trow = (const u64*)(w1Ts + l * 32);
        #pragma unroll
        for (int i = 0; i < 16; i++) wr[i] = w1Trow[i];
        #pragma unroll
        for (int i = 0; i < 16; i++) g[i] = 0ull;
        for (int k = 0; k < 32; k++) {
            const u64* xrow = (const u64*)(Sw + k * 32);    // broadcast reads
            u64 a0 = 0ull, a1 = 0ull;
            #pragma unroll
            for (int i = 0; i < 16; i += 2) {
                a0 = f2fma(xrow[i], wr[i], a0);
                a1 = f2fma(xrow[i + 1], wr[i + 1], a1);
            }
            float x0, y0, x1, y1; up2(a0, x0, y0); up2(a1, x1, y1);
            float tk = (x0 + y0) + (x1 + y1);                // T[k][l]
            u64 tk2 = pk2(tk, tk);
            const u64* w1row = (const u64*)(w1s + k * 32);   // broadcast reads
            #pragma unroll
            for (int i = 0; i < 16; i++) g[i] = f2fma(w1row[i], tk2, g[i]);
        }
    }
    __syncwarp();

    // ---- EVD #1 (one-sided Jacobi, packed registers) ----
    float n1 = jacobi1s_pk<16>(g, l, 0, SW32);
    float lam1 = sqrtf(fmaxf(n1, 1e-20f));
    float coef1 = sqrtf(fmaxf(lam1, 1e-4f)) / lam1;  // sqrt(clamped)/lam

    // ---- Mh[l][j] = coef1 * sum_i g[i] * w2[i][j]  (row l of 32x16), packed ----
    {
        u64 mh[8];
        #pragma unroll
        for (int j = 0; j < 8; j++) mh[j] = 0ull;
        #pragma unroll
        for (int i2 = 0; i2 < 16; i2++) {
            float glo, ghi; up2(g[i2], glo, ghi);
            u64 ga = pk2(glo, glo), gb = pk2(ghi, ghi);
            const u64* r0 = (const u64*)(w2s + (2 * i2) * 16);
            const u64* r1 = (const u64*)(w2s + (2 * i2 + 1) * 16);
            #pragma unroll
            for (int j = 0; j < 8; j++) {
                mh[j] = f2fma(ga, r0[j], mh[j]);
                mh[j] = f2fma(gb, r1[j], mh[j]);
            }
        }
        __syncwarp();
        #pragma unroll
        for (int j = 0; j < 8; j++) {
            float a, c2; up2(mh[j], a, c2);
            Sw[l * 17 + 2 * j]     = coef1 * a;   // stride 17: conflict-free
            Sw[l * 17 + 2 * j + 1] = coef1 * c2;
        }
        __syncwarp();
    }

    // ---- Y2 = Mh^T Mh (16x16); lane's column (mirrored across half-warps) ----
    const int l16 = l & 15;
    float g2s[16];
    {
        #pragma unroll
        for (int a = 0; a < 16; a++) g2s[a] = 0.f;
        for (int k = 0; k < 32; k++) {
            float mkl = Sw[k * 17 + l16];
            #pragma unroll
            for (int a = 0; a < 16; a++) g2s[a] = fmaf(Sw[k * 17 + a], mkl, g2s[a]);
        }
    }
    u64 g2[8];
    #pragma unroll
    for (int i = 0; i < 8; i++) g2[i] = pk2(g2s[2 * i], g2s[2 * i + 1]);

    // ---- EVD #2 (16x16, packed) ----
    float n2 = jacobi1s_pk<8>(g2, l16, l & 16, SW16);
    float lam2 = sqrtf(fmaxf(n2, 1e-20f));
    float coef2 = sqrtf(fmaxf(lam2, 1e-4f)) / lam2;

    // ---- M2[l16][j] = coef2 * sum_i g2[i] * w3[i][j]  (16x4) ----
    {
        float m2[4] = {0.f, 0.f, 0.f, 0.f};
        #pragma unroll
        for (int i2 = 0; i2 < 8; i2++) {
            float glo, ghi; up2(g2[i2], glo, ghi);
            #pragma unroll
            for (int j = 0; j < 4; j++) {
                m2[j] = fmaf(glo, w3s[(2 * i2) * 4 + j], m2[j]);
                m2[j] = fmaf(ghi, w3s[(2 * i2 + 1) * 4 + j], m2[j]);
            }
        }
        __syncwarp();
        if (l < 16) {
            #pragma unroll
            for (int j = 0; j < 4; j++) Sw[l * 5 + j] = coef2 * m2[j];
        }
        __syncwarp();
    }

    // ---- Y3 = M2^T M2 (4x4): lane l<16 computes entry (l>>2, l&3) ----
    if (l < 16) {
        int a = l >> 2, c = l & 3;
        float acc = 0.f;
        #pragma unroll
        for (int k = 0; k < 16; k++) acc = fmaf(Sw[k * 5 + a], Sw[k * 5 + c], acc);
        Sw[96 + l] = acc;
    }
    __syncwarp();

    // ---- lane 0: 4x4 LogEig (serial Jacobi), feat, fc, log_softmax ----
    if (l == 0) {
        float A[4][4], Vv[4][4];
        #pragma unroll
        for (int i = 0; i < 4; i++)
            #pragma unroll
            for (int j = 0; j < 4; j++) {
                A[i][j] = Sw[96 + i * 4 + j];
                Vv[i][j] = (i == j) ? 1.f : 0.f;
            }

#define ROT4(p, q)                                                          \
        {                                                                   \
            float apq = A[p][q];                                            \
            if (apq != 0.f) {                                               \
                float app = A[p][p], aqq = A[q][q];                         \
                float tau = (aqq - app) * 0.5f * frcp(apq);                 \
                float tt = frcp(fabsf(tau) + fsqrt_ap(fmaf(tau, tau, 1.f)));\
                if (tau < 0.f) tt = -tt;                                    \
                float c = frsqrt_ap(fmaf(tt, tt, 1.f)), s = tt * c;         \
                _Pragma("unroll")                                           \
                for (int j = 0; j < 4; j++) {                               \
                    float u = A[p][j], v = A[q][j];                         \
                    A[p][j] = c * u - s * v;                                \
                    A[q][j] = s * u + c * v;                                \
                }                                                           \
                _Pragma("unroll")                                           \
                for (int j = 0; j < 4; j++) {                               \
                    float u = A[j][p], v = A[j][q];                         \
                    A[j][p] = c * u - s * v;                                \
                    A[j][q] = s * u + c * v;                                \
                }                                                           \
                _Pragma("unroll")                                           \
                for (int j = 0; j < 4; j++) {                               \
                    float u = Vv[j][p], v = Vv[j][q];                       \
                    Vv[j][p] = c * u - s * v;                               \
                    Vv[j][q] = s * u + c * v;                               \
                }                                                           \
            }                                                               \
        }

        #pragma unroll
        for (int sw = 0; sw < SW4; sw++) {
            ROT4(0, 1); ROT4(0, 2); ROT4(0, 3);
            ROT4(1, 2); ROT4(1, 3); ROT4(2, 3);
        }
#undef ROT4

        float lg[4];
        #pragma unroll
        for (int k = 0; k < 4; k++) lg[k] = logf(fmaxf(A[k][k], 1e-10f));

        float feat[16];
        #pragma unroll
        for (int i = 0; i < 4; i++)
            #pragma unroll
            for (int j = 0; j < 4; j++) {
                float acc = 0.f;
                #pragma unroll
                for (int k = 0; k < 4; k++) acc += lg[k] * Vv[i][k] * Vv[j][k];
                feat[i * 4 + j] = acc;
            }

        float l0 = 0.f, l1 = 0.f;
        #pragma unroll
        for (int i = 0; i < 16; i++) {
            l0 += feat[i] * fcs[2 * i + 0];
            l1 += feat[i] * fcs[2 * i + 1];
        }
        float mx = fmaxf(l0, l1);
        float lse = mx + logf(expf(l0 - mx) + expf(l1 - mx));

        out[2 * (size_t)b + 0] = l0 - lse;
        out[2 * (size_t)b + 1] = l1 - lse;
        float* fo = out + (size_t)2 * B + (size_t)16 * b;
        #pragma unroll
        for (int t2 = 0; t2 < 16; t2++) fo[t2] = feat[t2];
    }
}

extern "C" void kernel_launch(void* const* d_in, const int* in_sizes, int n_in,
                              void* d_out, int out_size) {
    const float* x  = (const float*)d_in[0];
    const float* w1 = (const float*)d_in[1];
    const float* w2 = (const float*)d_in[2];
    const float* w3 = (const float*)d_in[3];
    const float* fc = (const float*)d_in[4];
    float* out = (float*)d_out;
    int B = in_sizes[0] / 1024;
    dim3 grid((B + NW - 1) / NW);
    spdnet_kernel<<<grid, 128>>>(x, w1, w2, w3, fc, out, B);
}

// round 14
// speedup vs baseline: 8.5949x; 1.0360x over previous
#include <cuda_runtime.h>
#include <math.h>

#define NW 4           // warps (matrices) per block
#define SW32 6         // sweeps for 32x32 one-sided Jacobi
#define SW16 6         // sweeps for 16x16
#define SW4  7         // sweeps for 4x4 (serial, lane 0)
#define FULLMASK 0xffffffffu

typedef unsigned long long u64;

// ---- packed f32x2 helpers (sm_103a FFMA2 path) ----
__device__ __forceinline__ u64 pk2(float lo, float hi) {
    u64 r; asm("mov.b64 %0,{%1,%2};" : "=l"(r) : "f"(lo), "f"(hi)); return r;
}
__device__ __forceinline__ void up2(u64 v, float& lo, float& hi) {
    asm("mov.b64 {%0,%1},%2;" : "=f"(lo), "=f"(hi) : "l"(v));
}
__device__ __forceinline__ u64 f2fma(u64 a, u64 b, u64 c) {
    u64 d; asm("fma.rn.f32x2 %0,%1,%2,%3;" : "=l"(d) : "l"(a), "l"(b), "l"(c)); return d;
}
__device__ __forceinline__ u64 f2mul(u64 a, u64 b) {
    u64 d; asm("mul.rn.f32x2 %0,%1,%2;" : "=l"(d) : "l"(a), "l"(b)); return d;
}
// ---- approx MUFU (single-instruction) ----
__device__ __forceinline__ float frcp(float x) {
    float r; asm("rcp.approx.f32 %0,%1;" : "=f"(r) : "f"(x)); return r;
}
__device__ __forceinline__ float fsqrt_ap(float x) {
    float r; asm("sqrt.approx.f32 %0,%1;" : "=f"(r) : "f"(x)); return r;
}
__device__ __forceinline__ float frsqrt_ap(float x) {
    float r; asm("rsqrt.approx.f32 %0,%1;" : "=f"(r) : "f"(x)); return r;
}

// One-sided parallel Jacobi, packed columns. Lane (idx+lanebase) holds column
// idx as N2 f32x2 registers. Tournament pairing (incremental, no modulo).
// Branchless rotation: approx-MUFU params; degenerate cases resolve to
// identity (d->0 => tau->inf => tt->0) except the exact-tie select.
// Returns final squared column norm (= lambda^2); eigvec = g / lambda.
template<int N2>
__device__ __forceinline__ float jacobi1s_pk(u64 (&g)[N2], int idx, int lanebase,
                                             int sweeps) {
    const int m = 2 * N2 - 1;  // odd
    float n_own = 0.f;
    for (int sw = 0; sw < sweeps; sw++) {
        // recompute own squared norm at sweep start (kills drift)
        {
            u64 a0 = 0ull, a1 = 0ull;
            #pragma unroll
            for (int i = 0; i < N2; i += 2) {
                a0 = f2fma(g[i], g[i], a0);
                a1 = f2fma(g[i + 1], g[i + 1], a1);
            }
            float x0, y0, x1, y1; up2(a0, x0, y0); up2(a1, x1, y1);
            n_own = (x0 + y0) + (x1 + y1);
        }
        int pb = (idx == 0) ? 0 : (m - idx);  // (2r - idx) mod m, incremental
        for (int r = 0; r < m; r++) {
            int p = (idx == m) ? r : ((pb == idx) ? m : pb);
            pb += 2; if (pb >= m) pb -= m;
            int src = p + lanebase;
            u64 t[N2];
            #pragma unroll
            for (int i = 0; i < N2; i++) t[i] = __shfl_sync(FULLMASK, g[i], src);
            float np = __shfl_sync(FULLMASK, n_own, src);
            // d = g . t  (bit-identical on both lanes of the pair)
            u64 b0 = 0ull, b1 = 0ull;
            #pragma unroll
            for (int i = 0; i < N2; i += 2) {
                b0 = f2fma(g[i], t[i], b0);
                b1 = f2fma(g[i + 1], t[i + 1], b1);
            }
            float x0, y0, x1, y1; up2(b0, x0, y0); up2(b1, x1, y1);
            float d = (x0 + y0) + (x1 + y1);
            // rotation params (exactly sign-mirrored on partner lane)
            float dn = (np - n_own) * 0.5f;          // exactly negated on partner
            float tau = dn * frcp(d);                // d==0 => +-inf (or NaN if tie)
            float st = fsqrt_ap(fmaf(tau, tau, 1.f));
            float tt = frcp(fabsf(tau) + st);        // tau inf => tt 0 => identity
            tt = (tau < 0.f) ? -tt : tt;
            if (np == n_own) tt = (idx < p) ? 1.f : -1.f;  // tie: 45-deg antisym
            float c = frsqrt_ap(fmaf(tt, tt, 1.f));  // identical on both lanes
            float s = tt * c;                        // sign-mirrored
            u64 cp = pk2(c, c), ns = pk2(-s, -s);
            #pragma unroll
            for (int i = 0; i < N2; i++) g[i] = f2fma(cp, g[i], f2mul(ns, t[i]));
            n_own = fmaf(c * c, n_own, fmaf(s * s, np, -2.f * c * s * d));
        }
    }
    u64 a0 = 0ull, a1 = 0ull;
    #pragma unroll
    for (int i = 0; i < N2; i += 2) {
        a0 = f2fma(g[i], g[i], a0);
        a1 = f2fma(g[i + 1], g[i + 1], a1);
    }
    float x0, y0, x1, y1; up2(a0, x0, y0); up2(a1, x1, y1);
    return (x0 + y0) + (x1 + y1);
}

__global__ void __launch_bounds__(128, 5)
spdnet_kernel(const float* __restrict__ x,
              const float* __restrict__ w1,
              const float* __restrict__ w2,
              const float* __restrict__ w3,
              const float* __restrict__ fc,
              float* __restrict__ out, int B) {
    __shared__ float S_sh[NW][32 * 32];   // per-warp staging (stride 32, u64-aligned rows)
    __shared__ float T_sh[NW][32 * 33];   // per-warp T staging (stride 33: col index < 33, no alias)
    __shared__ float w1s [32 * 32];       // w1 row-major
    __shared__ float w1Ts[32 * 32];       // w1 transposed (col l contiguous)
    __shared__ float w2s [32 * 16];
    __shared__ float w3s [16 * 4];
    __shared__ float fcs [16 * 2];

    const int tid = threadIdx.x;
    for (int i = tid; i < 32 * 32; i += 128) w1s[i] = w1[i];
    for (int i = tid; i < 32 * 32; i += 128)
        w1Ts[i] = w1[(i & 31) * 32 + (i >> 5)];  // conflict-free stores
    for (int i = tid; i < 32 * 16; i += 128) w2s[i] = w2[i];
    if (tid < 64) w3s[tid] = w3[tid];
    if (tid < 32) fcs[tid] = fc[tid];
    __syncthreads();

    const int w = tid >> 5;
    const int l = tid & 31;
    const int b = blockIdx.x * NW + w;
    if (b >= B) return;  // warp-uniform

    float* Sw = S_sh[w];
    float* Tw = T_sh[w];

    // ---- stage X (32x32), stride 32 (lane-stride-1 writes: conflict-free) ----
    const float* xb = x + (size_t)b * 1024;
    #pragma unroll
    for (int i = 0; i < 32; i++) Sw[i * 32 + l] = xb[i * 32 + l];
    __syncwarp();

    // ---- bilinear Y1 = w1^T X w1, two-phase via smem T staging ----
    // Phase A: T[k][l] = dot(X row k, w1 col l); same-lane smem RAW (no sync).
    // Stride 33 (> max column index 31): unique addresses, odd => conflict-free.
    {
        u64 wr[16];  // w1 column l, packed
        const u64* w1Trow = (const u64*)(w1Ts + l * 32);
        #pragma unroll
        for (int i = 0; i < 16; i++) wr[i] = w1Trow[i];
        for (int k = 0; k < 32; k++) {
            const u64* xrow = (const u64*)(Sw + k * 32);    // broadcast reads
            u64 a0 = 0ull, a1 = 0ull;
            #pragma unroll
            for (int i = 0; i < 16; i += 2) {
                a0 = f2fma(xrow[i], wr[i], a0);
                a1 = f2fma(xrow[i + 1], wr[i + 1], a1);
            }
            float x0, y0, x1, y1; up2(a0, x0, y0); up2(a1, x1, y1);
            Tw[k * 33 + l] = (x0 + y0) + (x1 + y1);          // T[k][l]
        }
    }
    // Phase B: g[i] = sum_k w1[k][i] * T[k][l]
    u64 g[16];
    {
        #pragma unroll
        for (int i = 0; i < 16; i++) g[i] = 0ull;
        for (int k = 0; k < 32; k++) {
            float tk = Tw[k * 33 + l];                       // own column, conflict-free
            u64 tk2 = pk2(tk, tk);
            const u64* w1row = (const u64*)(w1s + k * 32);   // broadcast reads
            #pragma unroll
            for (int i = 0; i < 16; i++) g[i] = f2fma(w1row[i], tk2, g[i]);
        }
    }
    __syncwarp();

    // ---- EVD #1 (one-sided Jacobi, packed registers) ----
    float n1 = jacobi1s_pk<16>(g, l, 0, SW32);
    float lam1 = sqrtf(fmaxf(n1, 1e-20f));
    float coef1 = sqrtf(fmaxf(lam1, 1e-4f)) / lam1;  // sqrt(clamped)/lam

    // ---- Mh[l][j] = coef1 * sum_i g[i] * w2[i][j]  (row l of 32x16), packed ----
    // Row-major rows of 16 + stride 17: all indices < 17, no alias.
    {
        u64 mh[8];
        #pragma unroll
        for (int j = 0; j < 8; j++) mh[j] = 0ull;
        #pragma unroll
        for (int i2 = 0; i2 < 16; i2++) {
            float glo, ghi; up2(g[i2], glo, ghi);
            u64 ga = pk2(glo, glo), gb = pk2(ghi, ghi);
            const u64* r0 = (const u64*)(w2s + (2 * i2) * 16);
            const u64* r1 = (const u64*)(w2s + (2 * i2 + 1) * 16);
            #pragma unroll
            for (int j = 0; j < 8; j++) {
                mh[j] = f2fma(ga, r0[j], mh[j]);
                mh[j] = f2fma(gb, r1[j], mh[j]);
            }
        }
        __syncwarp();
        #pragma unroll
        for (int j = 0; j < 8; j++) {
            float a, c2; up2(mh[j], a, c2);
            Tw[l * 17 + 2 * j]     = coef1 * a;   // stride 17: indices < 17, safe
            Tw[l * 17 + 2 * j + 1] = coef1 * c2;
        }
        __syncwarp();
    }

    // ---- Y2 = Mh^T Mh (16x16); lane's column (mirrored across half-warps) ----
    const int l16 = l & 15;
    float g2s[16];
    {
        #pragma unroll
        for (int a = 0; a < 16; a++) g2s[a] = 0.f;
        for (int k = 0; k < 32; k++) {
            float mkl = Tw[k * 17 + l16];
            #pragma unroll
            for (int a = 0; a < 16; a++) g2s[a] = fmaf(Tw[k * 17 + a], mkl, g2s[a]);
        }
    }
    u64 g2[8];
    #pragma unroll
    for (int i = 0; i < 8; i++) g2[i] = pk2(g2s[2 * i], g2s[2 * i + 1]);

    // ---- EVD #2 (16x16, packed) ----
    float n2 = jacobi1s_pk<8>(g2, l16, l & 16, SW16);
    float lam2 = sqrtf(fmaxf(n2, 1e-20f));
    float coef2 = sqrtf(fmaxf(lam2, 1e-4f)) / lam2;

    // ---- M2[l16][j] = coef2 * sum_i g2[i] * w3[i][j]  (16x4) ----
    {
        float m2[4] = {0.f, 0.f, 0.f, 0.f};
        #pragma unroll
        for (int i2 = 0; i2 < 8; i2++) {
            float glo, ghi; up2(g2[i2], glo, ghi);
            #pragma unroll
            for (int j = 0; j < 4; j++) {
                m2[j] = fmaf(glo, w3s[(2 * i2) * 4 + j], m2[j]);
                m2[j] = fmaf(ghi, w3s[(2 * i2 + 1) * 4 + j], m2[j]);
            }
        }
        __syncwarp();
        if (l < 16) {
            #pragma unroll
            for (int j = 0; j < 4; j++) Sw[l * 5 + j] = coef2 * m2[j];
        }
        __syncwarp();
    }

    // ---- Y3 = M2^T M2 (4x4): lane l<16 computes entry (l>>2, l&3) ----
    if (l < 16) {
        int a = l >> 2, c = l & 3;
        float acc = 0.f;
        #pragma unroll
        for (int k = 0; k < 16; k++) acc = fmaf(Sw[k * 5 + a], Sw[k * 5 + c], acc);
        Sw[96 + l] = acc;
    }
    __syncwarp();

    // ---- lane 0: 4x4 LogEig (serial Jacobi), feat, fc, log_softmax ----
    if (l == 0) {
        float A[4][4], Vv[4][4];
        #pragma unroll
        for (int i = 0; i < 4; i++)
            #pragma unroll
            for (int j = 0; j < 4; j++) {
                A[i][j] = Sw[96 + i * 4 + j];
                Vv[i][j] = (i == j) ? 1.f : 0.f;
            }

#define ROT4(p, q)                                                          \
        {                                                                   \
            float apq = A[p][q];                                            \
            if (apq != 0.f) {                                               \
                float app = A[p][p], aqq = A[q][q];                         \
                float tau = (aqq - app) * 0.5f * frcp(apq);                 \
                float tt = frcp(fabsf(tau) + fsqrt_ap(fmaf(tau, tau, 1.f)));\
                if (tau < 0.f) tt = -tt;                                    \
                float c = frsqrt_ap(fmaf(tt, tt, 1.f)), s = tt * c;         \
                _Pragma("unroll")                                           \
                for (int j = 0; j < 4; j++) {                               \
                    float u = A[p][j], v = A[q][j];                         \
                    A[p][j] = c * u - s * v;                                \
                    A[q][j] = s * u + c * v;                                \
                }                                                           \
                _Pragma("unroll")                                           \
                for (int j = 0; j < 4; j++) {                               \
                    float u = A[j][p], v = A[j][q];                         \
                    A[j][p] = c * u - s * v;                                \
                    A[j][q] = s * u + c * v;                                \
                }                                                           \
                _Pragma("unroll")                                           \
                for (int j = 0; j < 4; j++) {                               \
                    float u = Vv[j][p], v = Vv[j][q];                       \
                    Vv[j][p] = c * u - s * v;                               \
                    Vv[j][q] = s * u + c * v;                               \
                }                                                           \
            }                                                               \
        }

        #pragma unroll
        for (int sw = 0; sw < SW4; sw++) {
            ROT4(0, 1); ROT4(0, 2); ROT4(0, 3);
            ROT4(1, 2); ROT4(1, 3); ROT4(2, 3);
        }
#undef ROT4

        float lg[4];
        #pragma unroll
        for (int k = 0; k < 4; k++) lg[k] = logf(fmaxf(A[k][k], 1e-10f));

        float feat[16];
        #pragma unroll
        for (int i = 0; i < 4; i++)
            #pragma unroll
            for (int j = 0; j < 4; j++) {
                float acc = 0.f;
                #pragma unroll
                for (int k = 0; k < 4; k++) acc += lg[k] * Vv[i][k] * Vv[j][k];
                feat[i * 4 + j] = acc;
            }

        float l0 = 0.f, l1 = 0.f;
        #pragma unroll
        for (int i = 0; i < 16; i++) {
            l0 += feat[i] * fcs[2 * i + 0];
            l1 += feat[i] * fcs[2 * i + 1];
        }
        float mx = fmaxf(l0, l1);
        float lse = mx + logf(expf(l0 - mx) + expf(l1 - mx));

        out[2 * (size_t)b + 0] = l0 - lse;
        out[2 * (size_t)b + 1] = l1 - lse;
        float* fo = out + (size_t)2 * B + (size_t)16 * b;
        #pragma unroll
        for (int t2 = 0; t2 < 16; t2++) fo[t2] = feat[t2];
    }
}

extern "C" void kernel_launch(void* const* d_in, const int* in_sizes, int n_in,
                              void* d_out, int out_size) {
    const float* x  = (const float*)d_in[0];
    const float* w1 = (const float*)d_in[1];
    const float* w2 = (const float*)d_in[2];
    const float* w3 = (const float*)d_in[3];
    const float* fc = (const float*)d_in[4];
    float* out = (float*)d_out;
    int B = in_sizes[0] / 1024;
    dim3 grid((B + NW - 1) / NW);
    spdnet_kernel<<<grid, 128>>>(x, w1, w2, w3, fc, out, B);
}

// round 15
// speedup vs baseline: 9.5680x; 1.1132x over previous
#include <cuda_runtime.h>
#include <math.h>

#define NW 4           // warps per block; each warp handles TWO matrices
#define SW32 6         // sweeps for 32x32 one-sided Jacobi
#define SW16 6         // sweeps for 16x16
#define SW4  7         // sweeps for 4x4 (serial)
#define FULLMASK 0xffffffffu

typedef unsigned long long u64;

// ---- packed f32x2 helpers (sm_103a FFMA2 path) ----
__device__ __forceinline__ u64 pk2(float lo, float hi) {
    u64 r; asm("mov.b64 %0,{%1,%2};" : "=l"(r) : "f"(lo), "f"(hi)); return r;
}
__device__ __forceinline__ void up2(u64 v, float& lo, float& hi) {
    asm("mov.b64 {%0,%1},%2;" : "=f"(lo), "=f"(hi) : "l"(v));
}
__device__ __forceinline__ u64 f2fma(u64 a, u64 b, u64 c) {
    u64 d; asm("fma.rn.f32x2 %0,%1,%2,%3;" : "=l"(d) : "l"(a), "l"(b), "l"(c)); return d;
}
__device__ __forceinline__ u64 f2mul(u64 a, u64 b) {
    u64 d; asm("mul.rn.f32x2 %0,%1,%2;" : "=l"(d) : "l"(a), "l"(b)); return d;
}
// ---- approx MUFU (single-instruction) ----
__device__ __forceinline__ float frcp(float x) {
    float r; asm("rcp.approx.f32 %0,%1;" : "=f"(r) : "f"(x)); return r;
}
__device__ __forceinline__ float fsqrt_ap(float x) {
    float r; asm("sqrt.approx.f32 %0,%1;" : "=f"(r) : "f"(x)); return r;
}
__device__ __forceinline__ float frsqrt_ap(float x) {
    float r; asm("rsqrt.approx.f32 %0,%1;" : "=f"(r) : "f"(x)); return r;
}

template<int N2>
__device__ __forceinline__ float sqnorm_pk(const u64 (&g)[N2]) {
    u64 a0 = 0ull, a1 = 0ull;
    #pragma unroll
    for (int i = 0; i < N2; i += 2) {
        a0 = f2fma(g[i], g[i], a0);
        a1 = f2fma(g[i + 1], g[i + 1], a1);
    }
    float x0, y0, x1, y1; up2(a0, x0, y0); up2(a1, x1, y1);
    return (x0 + y0) + (x1 + y1);
}

// One round of one-sided Jacobi for one stream. Identical numerics to R13.
template<int N2>
__device__ __forceinline__ void jround_pk(u64 (&g)[N2], float& n_own,
                                          int src, int idx, int p) {
    u64 t[N2];
    #pragma unroll
    for (int i = 0; i < N2; i++) t[i] = __shfl_sync(FULLMASK, g[i], src);
    float np = __shfl_sync(FULLMASK, n_own, src);
    u64 b0 = 0ull, b1 = 0ull;
    #pragma unroll
    for (int i = 0; i < N2; i += 2) {
        b0 = f2fma(g[i], t[i], b0);
        b1 = f2fma(g[i + 1], t[i + 1], b1);
    }
    float x0, y0, x1, y1; up2(b0, x0, y0); up2(b1, x1, y1);
    float d = (x0 + y0) + (x1 + y1);
    float dn = (np - n_own) * 0.5f;          // exactly negated on partner
    float tau = dn * frcp(d);
    float st = fsqrt_ap(fmaf(tau, tau, 1.f));
    float tt = frcp(fabsf(tau) + st);
    tt = (tau < 0.f) ? -tt : tt;
    if (np == n_own) tt = (idx < p) ? 1.f : -1.f;  // tie: 45-deg antisym
    float c = frsqrt_ap(fmaf(tt, tt, 1.f));
    float s = tt * c;
    u64 cp = pk2(c, c), ns = pk2(-s, -s);
    #pragma unroll
    for (int i = 0; i < N2; i++) g[i] = f2fma(cp, g[i], f2mul(ns, t[i]));
    n_own = fmaf(c * c, n_own, fmaf(s * s, np, -2.f * c * s * d));
}

// Dual-stream driver: two independent matrices per warp (ILP x2).
template<int N2>
__device__ __forceinline__ void jacobi_dual(u64 (&gA)[N2], u64 (&gB)[N2],
                                            float& nA, float& nB,
                                            int idx, int lanebase, int sweeps) {
    const int m = 2 * N2 - 1;
    for (int sw = 0; sw < sweeps; sw++) {
        nA = sqnorm_pk(gA);
        nB = sqnorm_pk(gB);
        int pb = (idx == 0) ? 0 : (m - idx);
        for (int r = 0; r < m; r++) {
            int p = (idx == m) ? r : ((pb == idx) ? m : pb);
            pb += 2; if (pb >= m) pb -= m;
            int src = p + lanebase;
            jround_pk(gA, nA, src, idx, p);
            jround_pk(gB, nB, src, idx, p);
        }
    }
    nA = sqnorm_pk(gA);
    nB = sqnorm_pk(gB);
}

// Single-stream driver (EVD2: each half-warp holds a different matrix).
template<int N2>
__device__ __forceinline__ float jacobi_single(u64 (&g)[N2], int idx,
                                               int lanebase, int sweeps) {
    const int m = 2 * N2 - 1;
    float n = 0.f;
    for (int sw = 0; sw < sweeps; sw++) {
        n = sqnorm_pk(g);
        int pb = (idx == 0) ? 0 : (m - idx);
        for (int r = 0; r < m; r++) {
            int p = (idx == m) ? r : ((pb == idx) ? m : pb);
            pb += 2; if (pb >= m) pb -= m;
            jround_pk(g, n, p + lanebase, idx, p);
        }
    }
    return sqnorm_pk(g);
}

// Stage X and compute g = column l of w1^T X w1 (two-phase via Tw stride-33).
__device__ __forceinline__ void bilinear1(const float* __restrict__ xb,
                                          float* Sw, float* Tw,
                                          const float* w1s, const float* w1Ts,
                                          int l, u64 (&g)[16]) {
    #pragma unroll
    for (int i = 0; i < 32; i++) Sw[i * 32 + l] = xb[i * 32 + l];
    __syncwarp();
    {
        u64 wr[16];
        const u64* w1Trow = (const u64*)(w1Ts + l * 32);
        #pragma unroll
        for (int i = 0; i < 16; i++) wr[i] = w1Trow[i];
        for (int k = 0; k < 32; k++) {
            const u64* xrow = (const u64*)(Sw + k * 32);
            u64 a0 = 0ull, a1 = 0ull;
            #pragma unroll
            for (int i = 0; i < 16; i += 2) {
                a0 = f2fma(xrow[i], wr[i], a0);
                a1 = f2fma(xrow[i + 1], wr[i + 1], a1);
            }
            float x0, y0, x1, y1; up2(a0, x0, y0); up2(a1, x1, y1);
            Tw[k * 33 + l] = (x0 + y0) + (x1 + y1);   // stride 33: no alias, l<33
        }
    }
    #pragma unroll
    for (int i = 0; i < 16; i++) g[i] = 0ull;
    for (int k = 0; k < 32; k++) {
        float tk = Tw[k * 33 + l];                    // own column (same lane RAW)
        u64 tk2 = pk2(tk, tk);
        const u64* w1row = (const u64*)(w1s + k * 32);
        #pragma unroll
        for (int i = 0; i < 16; i++) g[i] = f2fma(w1row[i], tk2, g[i]);
    }
    __syncwarp();
}

// Mh = diag(coef) * (g-columns dotted into w2): row l of [32x16], stride 17.
__device__ __forceinline__ void make_mh(const u64 (&g)[16], float coef,
                                        const float* w2s, float* dst, int l) {
    u64 mh[8];
    #pragma unroll
    for (int j = 0; j < 8; j++) mh[j] = 0ull;
    #pragma unroll
    for (int i2 = 0; i2 < 16; i2++) {
        float glo, ghi; up2(g[i2], glo, ghi);
        u64 ga = pk2(glo, glo), gb = pk2(ghi, ghi);
        const u64* r0 = (const u64*)(w2s + (2 * i2) * 16);
        const u64* r1 = (const u64*)(w2s + (2 * i2 + 1) * 16);
        #pragma unroll
        for (int j = 0; j < 8; j++) {
            mh[j] = f2fma(ga, r0[j], mh[j]);
            mh[j] = f2fma(gb, r1[j], mh[j]);
        }
    }
    #pragma unroll
    for (int j = 0; j < 8; j++) {
        float a, c2; up2(mh[j], a, c2);
        dst[l * 17 + 2 * j]     = coef * a;   // indices < 17: safe at stride 17
        dst[l * 17 + 2 * j + 1] = coef * c2;
    }
}

__global__ void __launch_bounds__(128, 4)
spdnet_kernel(const float* __restrict__ x,
              const float* __restrict__ w1,
              const float* __restrict__ w2,
              const float* __restrict__ w3,
              const float* __restrict__ fc,
              float* __restrict__ out, int B) {
    __shared__ float S_sh[NW][32 * 32];   // staging / Mh_B / scratch
    __shared__ float T_sh[NW][32 * 33];   // bilinear T staging / Mh_A
    __shared__ float w1s [32 * 32];
    __shared__ float w1Ts[32 * 32];
    __shared__ float w2s [32 * 16];
    __shared__ float w3s [16 * 4];
    __shared__ float fcs [16 * 2];

    const int tid = threadIdx.x;
    for (int i = tid; i < 32 * 32; i += 128) w1s[i] = w1[i];
    for (int i = tid; i < 32 * 32; i += 128)
        w1Ts[i] = w1[(i & 31) * 32 + (i >> 5)];
    for (int i = tid; i < 32 * 16; i += 128) w2s[i] = w2[i];
    if (tid < 64) w3s[tid] = w3[tid];
    if (tid < 32) fcs[tid] = fc[tid];
    __syncthreads();

    const int w = tid >> 5;
    const int l = tid & 31;
    const int bA = 2 * (blockIdx.x * NW + w);
    const int bB = bA + 1;
    if (bA >= B) return;  // warp-uniform

    float* Sw = S_sh[w];
    float* Tw = T_sh[w];

    // ---- bilinears (sequential; tiles reused) ----
    u64 gA[16], gB[16];
    bilinear1(x + (size_t)bA * 1024, Sw, Tw, w1s, w1Ts, l, gA);
    bilinear1(x + (size_t)bB * 1024, Sw, Tw, w1s, w1Ts, l, gB);

    // ---- EVD #1: dual-stream (ILP x2) ----
    float nA, nB;
    jacobi_dual<16>(gA, gB, nA, nB, l, 0, SW32);
    float lamA = sqrtf(fmaxf(nA, 1e-20f));
    float lamB = sqrtf(fmaxf(nB, 1e-20f));
    float coefA = sqrtf(fmaxf(lamA, 1e-4f)) / lamA;
    float coefB = sqrtf(fmaxf(lamB, 1e-4f)) / lamB;

    // ---- Mh for both matrices: A -> Tw (s17), B -> Sw (s17) ----
    __syncwarp();
    make_mh(gA, coefA, w2s, Tw, l);
    make_mh(gB, coefB, w2s, Sw, l);
    __syncwarp();

    // ---- Y2 = Mh^T Mh (16x16): lower half-warp = A, upper = B ----
    const int l16 = l & 15;
    const float* mh = (l < 16) ? Tw : Sw;
    float g2s[16];
    #pragma unroll
    for (int a = 0; a < 16; a++) g2s[a] = 0.f;
    for (int k = 0; k < 32; k++) {
        float mkl = mh[k * 17 + l16];
        #pragma unroll
        for (int a = 0; a < 16; a++) g2s[a] = fmaf(mh[k * 17 + a], mkl, g2s[a]);
    }
    u64 g2[8];
    #pragma unroll
    for (int i = 0; i < 8; i++) g2[i] = pk2(g2s[2 * i], g2s[2 * i + 1]);

    // ---- EVD #2: each half-warp its own matrix (halved work) ----
    float n2 = jacobi_single<8>(g2, l16, l & 16, SW16);
    float lam2 = sqrtf(fmaxf(n2, 1e-20f));
    float coef2 = sqrtf(fmaxf(lam2, 1e-4f)) / lam2;

    // ---- M2 = coef2 * (g2 . w3)  [16x4] per half-warp ----
    const int half = l >> 4;           // 0 = A, 1 = B
    const int mb = 600 + half * 104;   // M2 scratch base in Sw
    {
        float m2[4] = {0.f, 0.f, 0.f, 0.f};
        #pragma unroll
        for (int i2 = 0; i2 < 8; i2++) {
            float glo, ghi; up2(g2[i2], glo, ghi);
            #pragma unroll
            for (int j = 0; j < 4; j++) {
                m2[j] = fmaf(glo, w3s[(2 * i2) * 4 + j], m2[j]);
                m2[j] = fmaf(ghi, w3s[(2 * i2 + 1) * 4 + j], m2[j]);
            }
        }
        __syncwarp();
        #pragma unroll
        for (int j = 0; j < 4; j++) Sw[mb + l16 * 5 + j] = coef2 * m2[j];
        __syncwarp();
    }

    // ---- Y3 = M2^T M2 (4x4) per half-warp: entry (l16>>2, l16&3) ----
    {
        int a = l16 >> 2, c = l16 & 3;
        float acc = 0.f;
        #pragma unroll
        for (int k = 0; k < 16; k++)
            acc = fmaf(Sw[mb + k * 5 + a], Sw[mb + k * 5 + c], acc);
        Sw[800 + half * 16 + l16] = acc;
    }
    __syncwarp();

    // ---- lanes 0 & 16: serial 4x4 LogEig + feat + fc + log_softmax ----
    if (l16 == 0) {
        const int yb = 800 + half * 16;
        const int b = bA + half;
        float A[4][4], Vv[4][4];
        #pragma unroll
        for (int i = 0; i < 4; i++)
            #pragma unroll
            for (int j = 0; j < 4; j++) {
                A[i][j] = Sw[yb + i * 4 + j];
                Vv[i][j] = (i == j) ? 1.f : 0.f;
            }

#define ROT4(p, q)                                                          \
        {                                                                   \
            float apq = A[p][q];                                            \
            if (apq != 0.f) {                                               \
                float app = A[p][p], aqq = A[q][q];                         \
                float tau = (aqq - app) * 0.5f * frcp(apq);                 \
                float tt = frcp(fabsf(tau) + fsqrt_ap(fmaf(tau, tau, 1.f)));\
                if (tau < 0.f) tt = -tt;                                    \
                float c = frsqrt_ap(fmaf(tt, tt, 1.f)), s = tt * c;         \
                _Pragma("unroll")                                           \
                for (int j = 0; j < 4; j++) {                               \
                    float u = A[p][j], v = A[q][j];                         \
                    A[p][j] = c * u - s * v;                                \
                    A[q][j] = s * u + c * v;                                \
                }                                                           \
                _Pragma("unroll")                                           \
                for (int j = 0; j < 4; j++) {                               \
                    float u = A[j][p], v = A[j][q];                         \
                    A[j][p] = c * u - s * v;                                \
                    A[j][q] = s * u + c * v;                                \
                }                                                           \
                _Pragma("unroll")                                           \
                for (int j = 0; j < 4; j++) {                               \
                    float u = Vv[j][p], v = Vv[j][q];                       \
                    Vv[j][p] = c * u - s * v;                               \
                    Vv[j][q] = s * u + c * v;                               \
                }                                                           \
            }                                                               \
        }

        #pragma unroll
        for (int sw = 0; sw < SW4; sw++) {
            ROT4(0, 1); ROT4(0, 2); ROT4(0, 3);
            ROT4(1, 2); ROT4(1, 3); ROT4(2, 3);
        }
#undef ROT4

        float lg[4];
        #pragma unroll
        for (int k = 0; k < 4; k++) lg[k] = logf(fmaxf(A[k][k], 1e-10f));

        float feat[16];
        #pragma unroll
        for (int i = 0; i < 4; i++)
            #pragma unroll
            for (int j = 0; j < 4; j++) {
                float acc = 0.f;
                #pragma unroll
                for (int k = 0; k < 4; k++) acc += lg[k] * Vv[i][k] * Vv[j][k];
                feat[i * 4 + j] = acc;
            }

        float l0 = 0.f, l1 = 0.f;
        #pragma unroll
        for (int i = 0; i < 16; i++) {
            l0 += feat[i] * fcs[2 * i + 0];
            l1 += feat[i] * fcs[2 * i + 1];
        }
        float mx = fmaxf(l0, l1);
        float lse = mx + logf(expf(l0 - mx) + expf(l1 - mx));

        out[2 * (size_t)b + 0] = l0 - lse;
        out[2 * (size_t)b + 1] = l1 - lse;
        float* fo = out + (size_t)2 * B + (size_t)16 * b;
        #pragma unroll
        for (int t2 = 0; t2 < 16; t2++) fo[t2] = feat[t2];
    }
}

extern "C" void kernel_launch(void* const* d_in, const int* in_sizes, int n_in,
                              void* d_out, int out_size) {
    const float* x  = (const float*)d_in[0];
    const float* w1 = (const float*)d_in[1];
    const float* w2 = (const float*)d_in[2];
    const float* w3 = (const float*)d_in[3];
    const float* fc = (const float*)d_in[4];
    float* out = (float*)d_out;
    int B = in_sizes[0] / 1024;
    dim3 grid((B + 2 * NW - 1) / (2 * NW));
    spdnet_kernel<<<grid, 128>>>(x, w1, w2, w3, fc, out, B);
}

// round 16
// speedup vs baseline: 9.9870x; 1.0438x over previous
#include <cuda_runtime.h>
#include <math.h>

#define NW 4           // warps per block; each warp handles TWO matrices
#define SW32 6         // sweeps for 32x32 one-sided Jacobi
#define SW16 6         // sweeps for 16x16
#define SW4  7         // sweeps for 4x4 (serial)
#define FULLMASK 0xffffffffu

typedef unsigned long long u64;

// ---- packed f32x2 helpers (sm_103a FFMA2 path) ----
__device__ __forceinline__ u64 pk2(float lo, float hi) {
    u64 r; asm("mov.b64 %0,{%1,%2};" : "=l"(r) : "f"(lo), "f"(hi)); return r;
}
__device__ __forceinline__ void up2(u64 v, float& lo, float& hi) {
    asm("mov.b64 {%0,%1},%2;" : "=f"(lo), "=f"(hi) : "l"(v));
}
__device__ __forceinline__ u64 f2fma(u64 a, u64 b, u64 c) {
    u64 d; asm("fma.rn.f32x2 %0,%1,%2,%3;" : "=l"(d) : "l"(a), "l"(b), "l"(c)); return d;
}
__device__ __forceinline__ u64 f2mul(u64 a, u64 b) {
    u64 d; asm("mul.rn.f32x2 %0,%1,%2;" : "=l"(d) : "l"(a), "l"(b)); return d;
}
// ---- approx MUFU (single-instruction) ----
__device__ __forceinline__ float frcp(float x) {
    float r; asm("rcp.approx.f32 %0,%1;" : "=f"(r) : "f"(x)); return r;
}
__device__ __forceinline__ float fsqrt_ap(float x) {
    float r; asm("sqrt.approx.f32 %0,%1;" : "=f"(r) : "f"(x)); return r;
}
__device__ __forceinline__ float frsqrt_ap(float x) {
    float r; asm("rsqrt.approx.f32 %0,%1;" : "=f"(r) : "f"(x)); return r;
}

template<int N2>
__device__ __forceinline__ float sqnorm_pk(const u64 (&g)[N2]) {
    u64 a0 = 0ull, a1 = 0ull;
    #pragma unroll
    for (int i = 0; i < N2; i += 2) {
        a0 = f2fma(g[i], g[i], a0);
        a1 = f2fma(g[i + 1], g[i + 1], a1);
    }
    float x0, y0, x1, y1; up2(a0, x0, y0); up2(a1, x1, y1);
    return (x0 + y0) + (x1 + y1);
}

// One round of one-sided Jacobi for one stream.
// 2-MUFU rotation: r = sqrt(dn^2+d^2); (u,v) = (dn+copysign(r,dn), d);
// (c,s) = (u,v)*rsqrt(u^2+v^2). v/u == classic tt exactly; when dn<0 the
// rotation is negated (column sign flip) which is harmless in one-sided
// Jacobi. Exact tie (np==n) gets an explicit mirrored 45-deg rotation.
template<int N2>
__device__ __forceinline__ void jround_pk(u64 (&g)[N2], float& n_own,
                                          int src, int idx, int p) {
    u64 t[N2];
    #pragma unroll
    for (int i = 0; i < N2; i++) t[i] = __shfl_sync(FULLMASK, g[i], src);
    float np = __shfl_sync(FULLMASK, n_own, src);
    u64 b0 = 0ull, b1 = 0ull;
    #pragma unroll
    for (int i = 0; i < N2; i += 2) {
        b0 = f2fma(g[i], t[i], b0);
        b1 = f2fma(g[i + 1], t[i + 1], b1);
    }
    float x0, y0, x1, y1; up2(b0, x0, y0); up2(b1, x1, y1);
    float d = (x0 + y0) + (x1 + y1);        // bit-identical on both pair lanes
    float dn = (np - n_own) * 0.5f;          // exactly negated on partner
    float r = fsqrt_ap(fmaf(dn, dn, d * d)); // MUFU #1
    float u = dn + copysignf(r, dn);
    float v = d;
    if (np == n_own) {                       // tie: mirrored 45-deg antisym
        u = fabsf(d);
        v = (idx < p) ? fabsf(d) : -fabsf(d);
    }
    float q2 = fmaf(u, u, v * v);
    float rr = frsqrt_ap(q2);                // MUFU #2
    bool ok = (q2 > 0.f);
    float c = ok ? u * rr : 1.f;
    float s = ok ? v * rr : 0.f;
    u64 cp = pk2(c, c), ns = pk2(-s, -s);
    #pragma unroll
    for (int i = 0; i < N2; i++) g[i] = f2fma(cp, g[i], f2mul(ns, t[i]));
    n_own = fmaf(c * c, n_own, fmaf(s * s, np, -2.f * c * s * d));
}

// Dual-stream driver: two independent matrices per warp (ILP x2).
template<int N2>
__device__ __forceinline__ void jacobi_dual(u64 (&gA)[N2], u64 (&gB)[N2],
                                            float& nA, float& nB,
                                            int idx, int lanebase, int sweeps) {
    const int m = 2 * N2 - 1;
    for (int sw = 0; sw < sweeps; sw++) {
        nA = sqnorm_pk(gA);
        nB = sqnorm_pk(gB);
        int pb = (idx == 0) ? 0 : (m - idx);
        for (int r = 0; r < m; r++) {
            int p = (idx == m) ? r : ((pb == idx) ? m : pb);
            pb += 2; if (pb >= m) pb -= m;
            int src = p + lanebase;
            jround_pk(gA, nA, src, idx, p);
            jround_pk(gB, nB, src, idx, p);
        }
    }
    nA = sqnorm_pk(gA);
    nB = sqnorm_pk(gB);
}

// Single-stream driver (EVD2: each half-warp holds a different matrix).
template<int N2>
__device__ __forceinline__ float jacobi_single(u64 (&g)[N2], int idx,
                                               int lanebase, int sweeps) {
    const int m = 2 * N2 - 1;
    float n = 0.f;
    for (int sw = 0; sw < sweeps; sw++) {
        n = sqnorm_pk(g);
        int pb = (idx == 0) ? 0 : (m - idx);
        for (int r = 0; r < m; r++) {
            int p = (idx == m) ? r : ((pb == idx) ? m : pb);
            pb += 2; if (pb >= m) pb -= m;
            jround_pk(g, n, p + lanebase, idx, p);
        }
    }
    return sqnorm_pk(g);
}

// Stage X and compute g = column l of w1^T X w1 (two-phase via Tw stride-33).
__device__ __forceinline__ void bilinear1(const float* __restrict__ xb,
                                          float* Sw, float* Tw,
                                          const float* w1s, const float* w1Ts,
                                          int l, u64 (&g)[16]) {
    #pragma unroll
    for (int i = 0; i < 32; i++) Sw[i * 32 + l] = xb[i * 32 + l];
    __syncwarp();
    {
        u64 wr[16];
        const u64* w1Trow = (const u64*)(w1Ts + l * 32);
        #pragma unroll
        for (int i = 0; i < 16; i++) wr[i] = w1Trow[i];
        for (int k = 0; k < 32; k++) {
            const u64* xrow = (const u64*)(Sw + k * 32);
            u64 a0 = 0ull, a1 = 0ull;
            #pragma unroll
            for (int i = 0; i < 16; i += 2) {
                a0 = f2fma(xrow[i], wr[i], a0);
                a1 = f2fma(xrow[i + 1], wr[i + 1], a1);
            }
            float x0, y0, x1, y1; up2(a0, x0, y0); up2(a1, x1, y1);
            Tw[k * 33 + l] = (x0 + y0) + (x1 + y1);   // stride 33: no alias, l<33
        }
    }
    #pragma unroll
    for (int i = 0; i < 16; i++) g[i] = 0ull;
    for (int k = 0; k < 32; k++) {
        float tk = Tw[k * 33 + l];                    // own column (same lane RAW)
        u64 tk2 = pk2(tk, tk);
        const u64* w1row = (const u64*)(w1s + k * 32);
        #pragma unroll
        for (int i = 0; i < 16; i++) g[i] = f2fma(w1row[i], tk2, g[i]);
    }
    __syncwarp();
}

// Mh = diag(coef) * (g-columns dotted into w2): row l of [32x16], stride 17.
__device__ __forceinline__ void make_mh(const u64 (&g)[16], float coef,
                                        const float* w2s, float* dst, int l) {
    u64 mh[8];
    #pragma unroll
    for (int j = 0; j < 8; j++) mh[j] = 0ull;
    #pragma unroll
    for (int i2 = 0; i2 < 16; i2++) {
        float glo, ghi; up2(g[i2], glo, ghi);
        u64 ga = pk2(glo, glo), gb = pk2(ghi, ghi);
        const u64* r0 = (const u64*)(w2s + (2 * i2) * 16);
        const u64* r1 = (const u64*)(w2s + (2 * i2 + 1) * 16);
        #pragma unroll
        for (int j = 0; j < 8; j++) {
            mh[j] = f2fma(ga, r0[j], mh[j]);
            mh[j] = f2fma(gb, r1[j], mh[j]);
        }
    }
    #pragma unroll
    for (int j = 0; j < 8; j++) {
        float a, c2; up2(mh[j], a, c2);
        dst[l * 17 + 2 * j]     = coef * a;   // indices < 17: safe at stride 17
        dst[l * 17 + 2 * j + 1] = coef * c2;
    }
}

__global__ void __launch_bounds__(128, 4)
spdnet_kernel(const float* __restrict__ x,
              const float* __restrict__ w1,
              const float* __restrict__ w2,
              const float* __restrict__ w3,
              const float* __restrict__ fc,
              float* __restrict__ out, int B) {
    __shared__ float S_sh[NW][32 * 32];   // staging / Mh_B / scratch
    __shared__ float T_sh[NW][32 * 33];   // bilinear T staging / Mh_A
    __shared__ float w1s [32 * 32];
    __shared__ float w1Ts[32 * 32];
    __shared__ float w2s [32 * 16];
    __shared__ float w3s [16 * 4];
    __shared__ float fcs [16 * 2];

    const int tid = threadIdx.x;
    for (int i = tid; i < 32 * 32; i += 128) w1s[i] = w1[i];
    for (int i = tid; i < 32 * 32; i += 128)
        w1Ts[i] = w1[(i & 31) * 32 + (i >> 5)];
    for (int i = tid; i < 32 * 16; i += 128) w2s[i] = w2[i];
    if (tid < 64) w3s[tid] = w3[tid];
    if (tid < 32) fcs[tid] = fc[tid];
    __syncthreads();

    const int w = tid >> 5;
    const int l = tid & 31;
    const int bA = 2 * (blockIdx.x * NW + w);
    const int bB = bA + 1;
    if (bA >= B) return;  // warp-uniform

    float* Sw = S_sh[w];
    float* Tw = T_sh[w];

    // ---- bilinears (sequential; tiles reused) ----
    u64 gA[16], gB[16];
    bilinear1(x + (size_t)bA * 1024, Sw, Tw, w1s, w1Ts, l, gA);
    bilinear1(x + (size_t)bB * 1024, Sw, Tw, w1s, w1Ts, l, gB);

    // ---- EVD #1: dual-stream (ILP x2) ----
    float nA, nB;
    jacobi_dual<16>(gA, gB, nA, nB, l, 0, SW32);
    float lamA = sqrtf(fmaxf(nA, 1e-20f));
    float lamB = sqrtf(fmaxf(nB, 1e-20f));
    float coefA = sqrtf(fmaxf(lamA, 1e-4f)) / lamA;
    float coefB = sqrtf(fmaxf(lamB, 1e-4f)) / lamB;

    // ---- Mh for both matrices: A -> Tw (s17), B -> Sw (s17) ----
    __syncwarp();
    make_mh(gA, coefA, w2s, Tw, l);
    make_mh(gB, coefB, w2s, Sw, l);
    __syncwarp();

    // ---- Y2 = Mh^T Mh (16x16): lower half-warp = A, upper = B ----
    const int l16 = l & 15;
    const float* mh = (l < 16) ? Tw : Sw;
    float g2s[16];
    #pragma unroll
    for (int a = 0; a < 16; a++) g2s[a] = 0.f;
    for (int k = 0; k < 32; k++) {
        float mkl = mh[k * 17 + l16];
        #pragma unroll
        for (int a = 0; a < 16; a++) g2s[a] = fmaf(mh[k * 17 + a], mkl, g2s[a]);
    }
    u64 g2[8];
    #pragma unroll
    for (int i = 0; i < 8; i++) g2[i] = pk2(g2s[2 * i], g2s[2 * i + 1]);

    // ---- EVD #2: each half-warp its own matrix (halved work) ----
    float n2 = jacobi_single<8>(g2, l16, l & 16, SW16);
    float lam2 = sqrtf(fmaxf(n2, 1e-20f));
    float coef2 = sqrtf(fmaxf(lam2, 1e-4f)) / lam2;

    // ---- M2 = coef2 * (g2 . w3)  [16x4] per half-warp ----
    const int half = l >> 4;           // 0 = A, 1 = B
    const int mb = 600 + half * 104;   // M2 scratch base in Sw
    {
        float m2[4] = {0.f, 0.f, 0.f, 0.f};
        #pragma unroll
        for (int i2 = 0; i2 < 8; i2++) {
            float glo, ghi; up2(g2[i2], glo, ghi);
            #pragma unroll
            for (int j = 0; j < 4; j++) {
                m2[j] = fmaf(glo, w3s[(2 * i2) * 4 + j], m2[j]);
                m2[j] = fmaf(ghi, w3s[(2 * i2 + 1) * 4 + j], m2[j]);
            }
        }
        __syncwarp();
        #pragma unroll
        for (int j = 0; j < 4; j++) Sw[mb + l16 * 5 + j] = coef2 * m2[j];
        __syncwarp();
    }

    // ---- Y3 = M2^T M2 (4x4) per half-warp: entry (l16>>2, l16&3) ----
    {
        int a = l16 >> 2, c = l16 & 3;
        float acc = 0.f;
        #pragma unroll
        for (int k = 0; k < 16; k++)
            acc = fmaf(Sw[mb + k * 5 + a], Sw[mb + k * 5 + c], acc);
        Sw[800 + half * 16 + l16] = acc;
    }
    __syncwarp();

    // ---- lanes 0 & 16: serial 4x4 LogEig + feat + fc + log_softmax ----
    if (l16 == 0) {
        const int yb = 800 + half * 16;
        const int b = bA + half;
        float A[4][4], Vv[4][4];
        #pragma unroll
        for (int i = 0; i < 4; i++)
            #pragma unroll
            for (int j = 0; j < 4; j++) {
                A[i][j] = Sw[yb + i * 4 + j];
                Vv[i][j] = (i == j) ? 1.f : 0.f;
            }

#define ROT4(p, q)                                                          \
        {                                                                   \
            float apq = A[p][q];                                            \
            if (apq != 0.f) {                                               \
                float app = A[p][p], aqq = A[q][q];                         \
                float tau = (aqq - app) * 0.5f * frcp(apq);                 \
                float tt = frcp(fabsf(tau) + fsqrt_ap(fmaf(tau, tau, 1.f)));\
                if (tau < 0.f) tt = -tt;                                    \
                float c = frsqrt_ap(fmaf(tt, tt, 1.f)), s = tt * c;         \
                _Pragma("unroll")                                           \
                for (int j = 0; j < 4; j++) {                               \
                    float u = A[p][j], v = A[q][j];                         \
                    A[p][j] = c * u - s * v;                                \
                    A[q][j] = s * u + c * v;                                \
                }                                                           \
                _Pragma("unroll")                                           \
                for (int j = 0; j < 4; j++) {                               \
                    float u = A[j][p], v = A[j][q];                         \
                    A[j][p] = c * u - s * v;                                \
                    A[j][q] = s * u + c * v;                                \
                }                                                           \
                _Pragma("unroll")                                           \
                for (int j = 0; j < 4; j++) {                               \
                    float u = Vv[j][p], v = Vv[j][q];                       \
                    Vv[j][p] = c * u - s * v;                               \
                    Vv[j][q] = s * u + c * v;                               \
                }                                                           \
            }                                                               \
        }

        #pragma unroll
        for (int sw = 0; sw < SW4; sw++) {
            ROT4(0, 1); ROT4(0, 2); ROT4(0, 3);
            ROT4(1, 2); ROT4(1, 3); ROT4(2, 3);
        }
#undef ROT4

        float lg[4];
        #pragma unroll
        for (int k = 0; k < 4; k++) lg[k] = logf(fmaxf(A[k][k], 1e-10f));

        float feat[16];
        #pragma unroll
        for (int i = 0; i < 4; i++)
            #pragma unroll
            for (int j = 0; j < 4; j++) {
                float acc = 0.f;
                #pragma unroll
                for (int k = 0; k < 4; k++) acc += lg[k] * Vv[i][k] * Vv[j][k];
                feat[i * 4 + j] = acc;
            }

        float l0 = 0.f, l1 = 0.f;
        #pragma unroll
        for (int i = 0; i < 16; i++) {
            l0 += feat[i] * fcs[2 * i + 0];
            l1 += feat[i] * fcs[2 * i + 1];
        }
        float mx = fmaxf(l0, l1);
        float lse = mx + logf(expf(l0 - mx) + expf(l1 - mx));

        out[2 * (size_t)b + 0] = l0 - lse;
        out[2 * (size_t)b + 1] = l1 - lse;
        float* fo = out + (size_t)2 * B + (size_t)16 * b;
        #pragma unroll
        for (int t2 = 0; t2 < 16; t2++) fo[t2] = feat[t2];
    }
}

extern "C" void kernel_launch(void* const* d_in, const int* in_sizes, int n_in,
                              void* d_out, int out_size) {
    const float* x  = (const float*)d_in[0];
    const float* w1 = (const float*)d_in[1];
    const float* w2 = (const float*)d_in[2];
    const float* w3 = (const float*)d_in[3];
    const float* fc = (const float*)d_in[4];
    float* out = (float*)d_out;
    int B = in_sizes[0] / 1024;
    dim3 grid((B + 2 * NW - 1) / (2 * NW));
    spdnet_kernel<<<grid, 128>>>(x, w1, w2, w3, fc, out, B);
}

// round 17
// speedup vs baseline: 11.3601x; 1.1375x over previous
#include <cuda_runtime.h>
#include <math.h>

#define NW 4           // warps per block; each warp handles TWO matrices
#define SW32 5         // sweeps for 32x32 one-sided Jacobi (probe: 6->5)
#define SW16 6         // sweeps for 16x16
#define SW4  7         // sweeps for 4x4 (serial)
#define FULLMASK 0xffffffffu

typedef unsigned long long u64;

// ---- packed f32x2 helpers (sm_103a FFMA2 path) ----
__device__ __forceinline__ u64 pk2(float lo, float hi) {
    u64 r; asm("mov.b64 %0,{%1,%2};" : "=l"(r) : "f"(lo), "f"(hi)); return r;
}
__device__ __forceinline__ void up2(u64 v, float& lo, float& hi) {
    asm("mov.b64 {%0,%1},%2;" : "=f"(lo), "=f"(hi) : "l"(v));
}
__device__ __forceinline__ u64 f2fma(u64 a, u64 b, u64 c) {
    u64 d; asm("fma.rn.f32x2 %0,%1,%2,%3;" : "=l"(d) : "l"(a), "l"(b), "l"(c)); return d;
}
__device__ __forceinline__ u64 f2mul(u64 a, u64 b) {
    u64 d; asm("mul.rn.f32x2 %0,%1,%2;" : "=l"(d) : "l"(a), "l"(b)); return d;
}
// ---- approx MUFU (single-instruction) ----
__device__ __forceinline__ float frcp(float x) {
    float r; asm("rcp.approx.f32 %0,%1;" : "=f"(r) : "f"(x)); return r;
}
__device__ __forceinline__ float fsqrt_ap(float x) {
    float r; asm("sqrt.approx.f32 %0,%1;" : "=f"(r) : "f"(x)); return r;
}
__device__ __forceinline__ float frsqrt_ap(float x) {
    float r; asm("rsqrt.approx.f32 %0,%1;" : "=f"(r) : "f"(x)); return r;
}

template<int N2>
__device__ __forceinline__ float sqnorm_pk(const u64 (&g)[N2]) {
    u64 a0 = 0ull, a1 = 0ull;
    #pragma unroll
    for (int i = 0; i < N2; i += 2) {
        a0 = f2fma(g[i], g[i], a0);
        a1 = f2fma(g[i + 1], g[i + 1], a1);
    }
    float x0, y0, x1, y1; up2(a0, x0, y0); up2(a1, x1, y1);
    return (x0 + y0) + (x1 + y1);
}

// One round of one-sided Jacobi for one stream.
// 2-MUFU rotation: r = sqrt(dn^2+d^2); (u,v) = (dn+copysign(r,dn), d);
// (c,s) = (u,v)*rsqrt(u^2+v^2). v/u == classic tt exactly; when dn<0 the
// rotation is negated (column sign flip) which is harmless in one-sided
// Jacobi. Exact tie (np==n) gets an explicit mirrored 45-deg rotation.
template<int N2>
__device__ __forceinline__ void jround_pk(u64 (&g)[N2], float& n_own,
                                          int src, int idx, int p) {
    u64 t[N2];
    #pragma unroll
    for (int i = 0; i < N2; i++) t[i] = __shfl_sync(FULLMASK, g[i], src);
    float np = __shfl_sync(FULLMASK, n_own, src);
    u64 b0 = 0ull, b1 = 0ull;
    #pragma unroll
    for (int i = 0; i < N2; i += 2) {
        b0 = f2fma(g[i], t[i], b0);
        b1 = f2fma(g[i + 1], t[i + 1], b1);
    }
    float x0, y0, x1, y1; up2(b0, x0, y0); up2(b1, x1, y1);
    float d = (x0 + y0) + (x1 + y1);        // bit-identical on both pair lanes
    float dn = (np - n_own) * 0.5f;          // exactly negated on partner
    float r = fsqrt_ap(fmaf(dn, dn, d * d)); // MUFU #1
    float u = dn + copysignf(r, dn);
    float v = d;
    if (np == n_own) {                       // tie: mirrored 45-deg antisym
        u = fabsf(d);
        v = (idx < p) ? fabsf(d) : -fabsf(d);
    }
    float q2 = fmaf(u, u, v * v);
    float rr = frsqrt_ap(q2);                // MUFU #2
    bool ok = (q2 > 0.f);
    float c = ok ? u * rr : 1.f;
    float s = ok ? v * rr : 0.f;
    u64 cp = pk2(c, c), ns = pk2(-s, -s);
    #pragma unroll
    for (int i = 0; i < N2; i++) g[i] = f2fma(cp, g[i], f2mul(ns, t[i]));
    n_own = fmaf(c * c, n_own, fmaf(s * s, np, -2.f * c * s * d));
}

// Dual-stream driver: two independent matrices per warp (ILP x2).
template<int N2>
__device__ __forceinline__ void jacobi_dual(u64 (&gA)[N2], u64 (&gB)[N2],
                                            float& nA, float& nB,
                                            int idx, int lanebase, int sweeps) {
    const int m = 2 * N2 - 1;
    for (int sw = 0; sw < sweeps; sw++) {
        nA = sqnorm_pk(gA);
        nB = sqnorm_pk(gB);
        int pb = (idx == 0) ? 0 : (m - idx);
        for (int r = 0; r < m; r++) {
            int p = (idx == m) ? r : ((pb == idx) ? m : pb);
            pb += 2; if (pb >= m) pb -= m;
            int src = p + lanebase;
            jround_pk(gA, nA, src, idx, p);
            jround_pk(gB, nB, src, idx, p);
        }
    }
    nA = sqnorm_pk(gA);
    nB = sqnorm_pk(gB);
}

// Single-stream driver (EVD2: each half-warp holds a different matrix).
template<int N2>
__device__ __forceinline__ float jacobi_single(u64 (&g)[N2], int idx,
                                               int lanebase, int sweeps) {
    const int m = 2 * N2 - 1;
    float n = 0.f;
    for (int sw = 0; sw < sweeps; sw++) {
        n = sqnorm_pk(g);
        int pb = (idx == 0) ? 0 : (m - idx);
        for (int r = 0; r < m; r++) {
            int p = (idx == m) ? r : ((pb == idx) ? m : pb);
            pb += 2; if (pb >= m) pb -= m;
            jround_pk(g, n, p + lanebase, idx, p);
        }
    }
    return sqnorm_pk(g);
}

// Stage X and compute g = column l of w1^T X w1 (two-phase via Tw stride-33).
__device__ __forceinline__ void bilinear1(const float* __restrict__ xb,
                                          float* Sw, float* Tw,
                                          const float* w1s, const float* w1Ts,
                                          int l, u64 (&g)[16]) {
    #pragma unroll
    for (int i = 0; i < 32; i++) Sw[i * 32 + l] = xb[i * 32 + l];
    __syncwarp();
    {
        u64 wr[16];
        const u64* w1Trow = (const u64*)(w1Ts + l * 32);
        #pragma unroll
        for (int i = 0; i < 16; i++) wr[i] = w1Trow[i];
        for (int k = 0; k < 32; k++) {
            const u64* xrow = (const u64*)(Sw + k * 32);
            u64 a0 = 0ull, a1 = 0ull;
            #pragma unroll
            for (int i = 0; i < 16; i += 2) {
                a0 = f2fma(xrow[i], wr[i], a0);
                a1 = f2fma(xrow[i + 1], wr[i + 1], a1);
            }
            float x0, y0, x1, y1; up2(a0, x0, y0); up2(a1, x1, y1);
            Tw[k * 33 + l] = (x0 + y0) + (x1 + y1);   // stride 33: no alias, l<33
        }
    }
    #pragma unroll
    for (int i = 0; i < 16; i++) g[i] = 0ull;
    for (int k = 0; k < 32; k++) {
        float tk = Tw[k * 33 + l];                    // own column (same lane RAW)
        u64 tk2 = pk2(tk, tk);
        const u64* w1row = (const u64*)(w1s + k * 32);
        #pragma unroll
        for (int i = 0; i < 16; i++) g[i] = f2fma(w1row[i], tk2, g[i]);
    }
    __syncwarp();
}

// Mh = diag(coef) * (g-columns dotted into w2): row l of [32x16], stride 17.
__device__ __forceinline__ void make_mh(const u64 (&g)[16], float coef,
                                        const float* w2s, float* dst, int l) {
    u64 mh[8];
    #pragma unroll
    for (int j = 0; j < 8; j++) mh[j] = 0ull;
    #pragma unroll
    for (int i2 = 0; i2 < 16; i2++) {
        float glo, ghi; up2(g[i2], glo, ghi);
        u64 ga = pk2(glo, glo), gb = pk2(ghi, ghi);
        const u64* r0 = (const u64*)(w2s + (2 * i2) * 16);
        const u64* r1 = (const u64*)(w2s + (2 * i2 + 1) * 16);
        #pragma unroll
        for (int j = 0; j < 8; j++) {
            mh[j] = f2fma(ga, r0[j], mh[j]);
            mh[j] = f2fma(gb, r1[j], mh[j]);
        }
    }
    #pragma unroll
    for (int j = 0; j < 8; j++) {
        float a, c2; up2(mh[j], a, c2);
        dst[l * 17 + 2 * j]     = coef * a;   // indices < 17: safe at stride 17
        dst[l * 17 + 2 * j + 1] = coef * c2;
    }
}

__global__ void __launch_bounds__(128, 4)
spdnet_kernel(const float* __restrict__ x,
              const float* __restrict__ w1,
              const float* __restrict__ w2,
              const float* __restrict__ w3,
              const float* __restrict__ fc,
              float* __restrict__ out, int B) {
    __shared__ float S_sh[NW][32 * 32];   // staging / Mh_B / scratch
    __shared__ float T_sh[NW][32 * 33];   // bilinear T staging / Mh_A
    __shared__ float w1s [32 * 32];
    __shared__ float w1Ts[32 * 32];
    __shared__ float w2s [32 * 16];
    __shared__ float w3s [16 * 4];
    __shared__ float fcs [16 * 2];

    const int tid = threadIdx.x;
    for (int i = tid; i < 32 * 32; i += 128) w1s[i] = w1[i];
    for (int i = tid; i < 32 * 32; i += 128)
        w1Ts[i] = w1[(i & 31) * 32 + (i >> 5)];
    for (int i = tid; i < 32 * 16; i += 128) w2s[i] = w2[i];
    if (tid < 64) w3s[tid] = w3[tid];
    if (tid < 32) fcs[tid] = fc[tid];
    __syncthreads();

    const int w = tid >> 5;
    const int l = tid & 31;
    const int bA = 2 * (blockIdx.x * NW + w);
    const int bB = bA + 1;
    if (bA >= B) return;  // warp-uniform

    float* Sw = S_sh[w];
    float* Tw = T_sh[w];

    // ---- bilinears (sequential; tiles reused) ----
    u64 gA[16], gB[16];
    bilinear1(x + (size_t)bA * 1024, Sw, Tw, w1s, w1Ts, l, gA);
    bilinear1(x + (size_t)bB * 1024, Sw, Tw, w1s, w1Ts, l, gB);

    // ---- EVD #1: dual-stream (ILP x2) ----
    float nA, nB;
    jacobi_dual<16>(gA, gB, nA, nB, l, 0, SW32);
    float lamA = sqrtf(fmaxf(nA, 1e-20f));
    float lamB = sqrtf(fmaxf(nB, 1e-20f));
    float coefA = sqrtf(fmaxf(lamA, 1e-4f)) / lamA;
    float coefB = sqrtf(fmaxf(lamB, 1e-4f)) / lamB;

    // ---- Mh for both matrices: A -> Tw (s17), B -> Sw (s17) ----
    __syncwarp();
    make_mh(gA, coefA, w2s, Tw, l);
    make_mh(gB, coefB, w2s, Sw, l);
    __syncwarp();

    // ---- Y2 = Mh^T Mh (16x16): lower half-warp = A, upper = B ----
    const int l16 = l & 15;
    const float* mh = (l < 16) ? Tw : Sw;
    float g2s[16];
    #pragma unroll
    for (int a = 0; a < 16; a++) g2s[a] = 0.f;
    for (int k = 0; k < 32; k++) {
        float mkl = mh[k * 17 + l16];
        #pragma unroll
        for (int a = 0; a < 16; a++) g2s[a] = fmaf(mh[k * 17 + a], mkl, g2s[a]);
    }
    u64 g2[8];
    #pragma unroll
    for (int i = 0; i < 8; i++) g2[i] = pk2(g2s[2 * i], g2s[2 * i + 1]);

    // ---- EVD #2: each half-warp its own matrix (halved work) ----
    float n2 = jacobi_single<8>(g2, l16, l & 16, SW16);
    float lam2 = sqrtf(fmaxf(n2, 1e-20f));
    float coef2 = sqrtf(fmaxf(lam2, 1e-4f)) / lam2;

    // ---- M2 = coef2 * (g2 . w3)  [16x4] per half-warp ----
    const int half = l >> 4;           // 0 = A, 1 = B
    const int mb = 600 + half * 104;   // M2 scratch base in Sw
    {
        float m2[4] = {0.f, 0.f, 0.f, 0.f};
        #pragma unroll
        for (int i2 = 0; i2 < 8; i2++) {
            float glo, ghi; up2(g2[i2], glo, ghi);
            #pragma unroll
            for (int j = 0; j < 4; j++) {
                m2[j] = fmaf(glo, w3s[(2 * i2) * 4 + j], m2[j]);
                m2[j] = fmaf(ghi, w3s[(2 * i2 + 1) * 4 + j], m2[j]);
            }
        }
        __syncwarp();
        #pragma unroll
        for (int j = 0; j < 4; j++) Sw[mb + l16 * 5 + j] = coef2 * m2[j];
        __syncwarp();
    }

    // ---- Y3 = M2^T M2 (4x4) per half-warp: entry (l16>>2, l16&3) ----
    {
        int a = l16 >> 2, c = l16 & 3;
        float acc = 0.f;
        #pragma unroll
        for (int k = 0; k < 16; k++)
            acc = fmaf(Sw[mb + k * 5 + a], Sw[mb + k * 5 + c], acc);
        Sw[800 + half * 16 + l16] = acc;
    }
    __syncwarp();

    // ---- lanes 0 & 16: serial 4x4 LogEig + feat + fc + log_softmax ----
    if (l16 == 0) {
        const int yb = 800 + half * 16;
        const int b = bA + half;
        float A[4][4], Vv[4][4];
        #pragma unroll
        for (int i = 0; i < 4; i++)
            #pragma unroll
            for (int j = 0; j < 4; j++) {
                A[i][j] = Sw[yb + i * 4 + j];
                Vv[i][j] = (i == j) ? 1.f : 0.f;
            }

#define ROT4(p, q)                                                          \
        {                                                                   \
            float apq = A[p][q];                                            \
            if (apq != 0.f) {                                               \
                float app = A[p][p], aqq = A[q][q];                         \
                float tau = (aqq - app) * 0.5f * frcp(apq);                 \
                float tt = frcp(fabsf(tau) + fsqrt_ap(fmaf(tau, tau, 1.f)));\
                if (tau < 0.f) tt = -tt;                                    \
                float c = frsqrt_ap(fmaf(tt, tt, 1.f)), s = tt * c;         \
                _Pragma("unroll")                                           \
                for (int j = 0; j < 4; j++) {                               \
                    float u = A[p][j], v = A[q][j];                         \
                    A[p][j] = c * u - s * v;                                \
                    A[q][j] = s * u + c * v;                                \
                }                                                           \
                _Pragma("unroll")                                           \
                for (int j = 0; j < 4; j++) {                               \
                    float u = A[j][p], v = A[j][q];                         \
                    A[j][p] = c * u - s * v;                                \
                    A[j][q] = s * u + c * v;                                \
                }                                                           \
                _Pragma("unroll")                                           \
                for (int j = 0; j < 4; j++) {                               \
                    float u = Vv[j][p], v = Vv[j][q];                       \
                    Vv[j][p] = c * u - s * v;                               \
                    Vv[j][q] = s * u + c * v;                               \
                }                                                           \
            }                                                               \
        }

        #pragma unroll
        for (int sw = 0; sw < SW4; sw++) {
            ROT4(0, 1); ROT4(0, 2); ROT4(0, 3);
            ROT4(1, 2); ROT4(1, 3); ROT4(2, 3);
        }
#undef ROT4

        float lg[4];
        #pragma unroll
        for (int k = 0; k < 4; k++) lg[k] = logf(fmaxf(A[k][k], 1e-10f));

        float feat[16];
        #pragma unroll
        for (int i = 0; i < 4; i++)
            #pragma unroll
            for (int j = 0; j < 4; j++) {
                float acc = 0.f;
                #pragma unroll
                for (int k = 0; k < 4; k++) acc += lg[k] * Vv[i][k] * Vv[j][k];
                feat[i * 4 + j] = acc;
            }

        float l0 = 0.f, l1 = 0.f;
        #pragma unroll
        for (int i = 0; i < 16; i++) {
            l0 += feat[i] * fcs[2 * i + 0];
            l1 += feat[i] * fcs[2 * i + 1];
        }
        float mx = fmaxf(l0, l1);
        float lse = mx + logf(expf(l0 - mx) + expf(l1 - mx));

        out[2 * (size_t)b + 0] = l0 - lse;
        out[2 * (size_t)b + 1] = l1 - lse;
        float* fo = out + (size_t)2 * B + (size_t)16 * b;
        #pragma unroll
        for (int t2 = 0; t2 < 16; t2++) fo[t2] = feat[t2];
    }
}

extern "C" void kernel_launch(void* const* d_in, const int* in_sizes, int n_in,
                              void* d_out, int out_size) {
    const float* x  = (const float*)d_in[0];
    const float* w1 = (const float*)d_in[1];
    const float* w2 = (const float*)d_in[2];
    const float* w3 = (const float*)d_in[3];
    const float* fc = (const float*)d_in[4];
    float* out = (float*)d_out;
    int B = in_sizes[0] / 1024;
    dim3 grid((B + 2 * NW - 1) / (2 * NW));
    spdnet_kernel<<<grid, 128>>>(x, w1, w2, w3, fc, out, B);
}